// round 1
// baseline (speedup 1.0000x reference)
#include <cuda_runtime.h>
#include <math.h>

#define BB 128
#define TT 256
#define INDIM 512
#define CC 2048
#define NN 256
#define MM 128
#define OUTD 512
#define KH 640            // MM + INDIM
#define PR 134            // M+6
#define PWD 390           // 3M+6
#define PDIM 1036         // PR + PWD + OUTD
#define EPSF 1e-8f

// -------- persistent device state (scratch) --------
__device__ float g_h[BB*CC];          // hidden (B, C)
__device__ float g_p[BB*PDIM];        // projections (B, 1036)
__device__ float g_r[BB*MM];          // read vector
__device__ float g_wr[BB*NN];         // read weights
__device__ float g_ww[BB*NN];         // write weights
__device__ float g_mem[BB*NN*MM];     // memory (B, N, M)
__device__ float g_Wall[CC*PDIM];     // packed [Wr | Ww | Wout]
__device__ float g_ball[PDIM];

// -------- helpers --------
__device__ __forceinline__ float sigmoidf_(float x) { return 1.f / (1.f + expf(-x)); }
__device__ __forceinline__ float softplusf_(float x) {
    return fmaxf(x, 0.f) + log1pf(expf(-fabsf(x)));
}

// -------- init kernels --------
__global__ void pack_w_kernel(const float* __restrict__ Wr, const float* __restrict__ br,
                              const float* __restrict__ Ww, const float* __restrict__ bw,
                              const float* __restrict__ Wout, const float* __restrict__ bout) {
    int gid = blockIdx.x * blockDim.x + threadIdx.x;
    int stride = gridDim.x * blockDim.x;
    // bias
    for (int i = gid; i < PDIM; i += stride) {
        float v;
        if (i < PR) v = br[i];
        else if (i < PR + PWD) v = bw[i - PR];
        else v = bout[i - PR - PWD];
        g_ball[i] = v;
    }
    // packed weights, row-major (C, PDIM)
    int total = CC * PDIM;
    for (int idx = gid; idx < total; idx += stride) {
        int row = idx / PDIM, col = idx % PDIM;
        float v;
        if (col < PR) v = Wr[row * PR + col];
        else if (col < PR + PWD) v = Ww[row * PWD + (col - PR)];
        else v = Wout[row * OUTD + (col - PR - PWD)];
        g_Wall[idx] = v;
    }
}

__global__ void init_state_kernel(const float* __restrict__ mem_init,
                                  const float* __restrict__ read_init) {
    int gid = blockIdx.x * blockDim.x + threadIdx.x;
    int stride = gridDim.x * blockDim.x;
    const int memsz = BB * NN * MM;
    for (int i = gid; i < memsz; i += stride) g_mem[i] = mem_init[i % (NN * MM)];
    for (int i = gid; i < BB * NN; i += stride) { g_wr[i] = 1.f / NN; g_ww[i] = 1.f / NN; }
    for (int i = gid; i < BB * MM; i += stride) g_r[i] = read_init[i % MM];
}

// -------- GEMM 1: h = tanh([r, x_t] @ Wc + bc)   (128 x 640 @ 640 x 2048) --------
// tiles: BM=32, BN=64, BK=16; 16x16 threads; 2x4 micro-tile
__global__ void __launch_bounds__(256) gemm_h_kernel(const float* __restrict__ x,
                                                     const float* __restrict__ Wc,
                                                     const float* __restrict__ bc, int t) {
    __shared__ float As[16][34];   // [k][m], padded
    __shared__ float Bs[16][64];   // [k][n]
    const int tx = threadIdx.x, ty = threadIdx.y;
    const int tid = ty * 16 + tx;
    const int row0 = blockIdx.y * 32;
    const int col0 = blockIdx.x * 64;

    float acc[2][4] = {{0.f,0.f,0.f,0.f},{0.f,0.f,0.f,0.f}};

    for (int k0 = 0; k0 < KH; k0 += 16) {
        // A tile: 32x16 (m-major groups of 16 k's -> coalesced 64B per row chunk)
        #pragma unroll
        for (int i = 0; i < 2; i++) {
            int e = tid + i * 256;
            int m = e >> 4, kk = e & 15;
            int b = row0 + m, k = k0 + kk;
            float v = (k < MM) ? g_r[b * MM + k]
                               : x[((long long)b * TT + t) * INDIM + (k - MM)];
            As[kk][m] = v;
        }
        // B tile: 16x64
        #pragma unroll
        for (int i = 0; i < 4; i++) {
            int e = tid + i * 256;
            int kk = e >> 6, n = e & 63;
            Bs[kk][n] = Wc[(k0 + kk) * CC + col0 + n];
        }
        __syncthreads();
        #pragma unroll
        for (int kk = 0; kk < 16; kk++) {
            float a0 = As[kk][ty * 2 + 0];
            float a1 = As[kk][ty * 2 + 1];
            float b0 = Bs[kk][tx * 4 + 0];
            float b1 = Bs[kk][tx * 4 + 1];
            float b2 = Bs[kk][tx * 4 + 2];
            float b3 = Bs[kk][tx * 4 + 3];
            acc[0][0] += a0 * b0; acc[0][1] += a0 * b1; acc[0][2] += a0 * b2; acc[0][3] += a0 * b3;
            acc[1][0] += a1 * b0; acc[1][1] += a1 * b1; acc[1][2] += a1 * b2; acc[1][3] += a1 * b3;
        }
        __syncthreads();
    }
    #pragma unroll
    for (int i = 0; i < 2; i++) {
        int b = row0 + ty * 2 + i;
        #pragma unroll
        for (int j = 0; j < 4; j++) {
            int c = col0 + tx * 4 + j;
            g_h[b * CC + c] = tanhf(acc[i][j] + bc[c]);
        }
    }
}

// -------- GEMM 2: p = h @ Wall + ball   (128 x 2048 @ 2048 x 1036) --------
__global__ void __launch_bounds__(256) gemm_p_kernel(float* __restrict__ out, int t) {
    __shared__ float As[16][34];
    __shared__ float Bs[16][64];
    const int tx = threadIdx.x, ty = threadIdx.y;
    const int tid = ty * 16 + tx;
    const int row0 = blockIdx.y * 32;
    const int col0 = blockIdx.x * 64;

    float acc[2][4] = {{0.f,0.f,0.f,0.f},{0.f,0.f,0.f,0.f}};

    for (int k0 = 0; k0 < CC; k0 += 16) {
        #pragma unroll
        for (int i = 0; i < 2; i++) {
            int e = tid + i * 256;
            int m = e >> 4, kk = e & 15;
            As[kk][m] = g_h[(row0 + m) * CC + k0 + kk];
        }
        #pragma unroll
        for (int i = 0; i < 4; i++) {
            int e = tid + i * 256;
            int kk = e >> 6, n = e & 63;
            int col = col0 + n;
            Bs[kk][n] = (col < PDIM) ? g_Wall[(k0 + kk) * PDIM + col] : 0.f;
        }
        __syncthreads();
        #pragma unroll
        for (int kk = 0; kk < 16; kk++) {
            float a0 = As[kk][ty * 2 + 0];
            float a1 = As[kk][ty * 2 + 1];
            float b0 = Bs[kk][tx * 4 + 0];
            float b1 = Bs[kk][tx * 4 + 1];
            float b2 = Bs[kk][tx * 4 + 2];
            float b3 = Bs[kk][tx * 4 + 3];
            acc[0][0] += a0 * b0; acc[0][1] += a0 * b1; acc[0][2] += a0 * b2; acc[0][3] += a0 * b3;
            acc[1][0] += a1 * b0; acc[1][1] += a1 * b1; acc[1][2] += a1 * b2; acc[1][3] += a1 * b3;
        }
        __syncthreads();
    }
    #pragma unroll
    for (int i = 0; i < 2; i++) {
        int b = row0 + ty * 2 + i;
        #pragma unroll
        for (int j = 0; j < 4; j++) {
            int c = col0 + tx * 4 + j;
            if (c < PDIM) {
                float v = acc[i][j] + g_ball[c];
                if (c < PR + PWD) {
                    g_p[b * PDIM + c] = v;
                } else {
                    out[((long long)b * TT + t) * OUTD + (c - PR - PWD)] = v;
                }
            }
        }
    }
}

// -------- fused NTM step: read/write addressing, read vector, memory update --------
__device__ __forceinline__ float block_reduce_sum(float v, float* red, int tid) {
    red[tid] = v; __syncthreads();
    #pragma unroll
    for (int s = 128; s > 0; s >>= 1) {
        if (tid < s) red[tid] += red[tid + s];
        __syncthreads();
    }
    float r = red[0]; __syncthreads();
    return r;
}

__device__ __forceinline__ float block_reduce_max(float v, float* red, int tid) {
    red[tid] = v; __syncthreads();
    #pragma unroll
    for (int s = 128; s > 0; s >>= 1) {
        if (tid < s) red[tid] = fmaxf(red[tid], red[tid + s]);
        __syncthreads();
    }
    float r = red[0]; __syncthreads();
    return r;
}

// pp: smem pointer to 134 addressing params; gw: global prev/next weights for this batch
// s_mem: this batch's memory (N*M floats in smem); result weight left in s_w and gw.
__device__ void address_fn(const float* __restrict__ pp, float* __restrict__ gw,
                           const float* __restrict__ s_mem,
                           float* __restrict__ s_w, float* __restrict__ s_red, int tid) {
    // key norm
    float kv = (tid < MM) ? pp[tid] : 0.f;
    float knorm = sqrtf(block_reduce_sum(kv * kv, s_red, tid));
    float beta  = softplusf_(pp[MM]);
    float gg    = sigmoidf_(pp[MM + 1]);
    float p2 = pp[MM + 2], p3 = pp[MM + 3], p4 = pp[MM + 4];
    float smax = fmaxf(p2, fmaxf(p3, p4));
    float e0 = expf(p2 - smax), e1 = expf(p3 - smax), e2 = expf(p4 - smax);
    float einv = 1.f / (e0 + e1 + e2);
    float s0 = e0 * einv, s1 = e1 * einv, s2 = e2 * einv;
    float gamma = 1.f + softplusf_(pp[MM + 5]);

    // cosine similarity for row n = tid (lane-skewed smem access, conflict-free)
    float dot = 0.f, msq = 0.f;
    const int base = tid * MM;
    #pragma unroll 8
    for (int j = 0; j < MM; j++) {
        int m = (j + tid) & (MM - 1);
        float v = s_mem[base + m];
        dot += pp[m] * v;
        msq += v * v;
    }
    float sim = dot / (knorm * sqrtf(msq) + EPSF);

    // softmax(beta * sim)
    float z = beta * sim;
    float zmax = block_reduce_max(z, s_red, tid);
    float ez = expf(z - zmax);
    float zsum = block_reduce_sum(ez, s_red, tid);
    float wc = ez / zsum;

    // interpolation
    float wprev = gw[tid];
    float wg = gg * wc + (1.f - gg) * wprev;
    s_w[tid] = wg;
    __syncthreads();

    // circular shift + sharpen
    float wt = s_w[(tid + 1) & (NN - 1)] * s0 + wg * s1 + s_w[(tid + NN - 1) & (NN - 1)] * s2;
    float wp = powf(wt + EPSF, gamma);
    float wsum = block_reduce_sum(wp, s_red, tid);
    float wn = wp / wsum;
    __syncthreads();
    s_w[tid] = wn;
    gw[tid] = wn;
    __syncthreads();
}

extern __shared__ float s_mem[];  // NN*MM floats (128 KB)

__global__ void __launch_bounds__(256) ntm_step_kernel() {
    const int b = blockIdx.x;
    const int tid = threadIdx.x;

    __shared__ float s_p[PR + PWD];   // 524
    __shared__ float s_w[NN];
    __shared__ float s_red[NN];
    __shared__ float s_e[MM];
    __shared__ float s_a[MM];

    // load projections
    for (int i = tid; i < PR + PWD; i += 256) s_p[i] = g_p[b * PDIM + i];
    // stage memory into smem (coalesced float4)
    {
        const float4* gm4 = reinterpret_cast<const float4*>(g_mem + (size_t)b * NN * MM);
        float4* sm4 = reinterpret_cast<float4*>(s_mem);
        #pragma unroll 4
        for (int i = tid; i < NN * MM / 4; i += 256) sm4[i] = gm4[i];
    }
    // e, a from write projection
    __syncthreads();
    if (tid < MM) {
        s_e[tid] = sigmoidf_(s_p[PR + PR + tid]);          // pw[134 + m]
        s_a[tid] = tanhf(s_p[PR + 2 * MM + 6 + tid]);      // pw[262 + m]
    }
    __syncthreads();

    // ---- read addressing (uses old mem) ----
    address_fn(s_p, g_wr + b * NN, s_mem, s_w, s_red, tid);

    // ---- read vector: r[m] = sum_n w_r[n] * mem[n][m] ----
    {
        int m = tid & (MM - 1);
        int half = tid >> 7;   // 0 or 1
        float acc = 0.f;
        int n0 = half * 128;
        #pragma unroll 8
        for (int n = n0; n < n0 + 128; n++) acc += s_w[n] * s_mem[n * MM + m];
        s_red[tid] = acc;
        __syncthreads();
        if (tid < MM) g_r[b * MM + tid] = s_red[tid] + s_red[tid + 128];
        __syncthreads();
    }

    // ---- write addressing (uses old mem) ----
    address_fn(s_p + PR, g_ww + b * NN, s_mem, s_w, s_red, tid);

    // ---- memory update ----
    {
        float* gmo = g_mem + (size_t)b * NN * MM;
        #pragma unroll 4
        for (int idx = tid; idx < NN * MM; idx += 256) {
            int n = idx >> 7, m = idx & (MM - 1);
            float wwn = s_w[n];
            float old = s_mem[idx];
            gmo[idx] = old * (1.f - wwn * s_e[m]) + wwn * s_a[m];
        }
    }
}

// -------- launch --------
extern "C" void kernel_launch(void* const* d_in, const int* in_sizes, int n_in,
                              void* d_out, int out_size) {
    const float* x        = (const float*)d_in[0];
    const float* Wc       = (const float*)d_in[1];
    const float* bc       = (const float*)d_in[2];
    const float* Wout     = (const float*)d_in[3];
    const float* bout     = (const float*)d_in[4];
    const float* Wr       = (const float*)d_in[5];
    const float* br       = (const float*)d_in[6];
    const float* Ww       = (const float*)d_in[7];
    const float* bw       = (const float*)d_in[8];
    const float* mem_init = (const float*)d_in[9];
    const float* read_init= (const float*)d_in[10];
    float* out = (float*)d_out;
    (void)in_sizes; (void)n_in; (void)out_size;

    cudaFuncSetAttribute(ntm_step_kernel, cudaFuncAttributeMaxDynamicSharedMemorySize,
                         NN * MM * (int)sizeof(float));

    pack_w_kernel<<<256, 256>>>(Wr, br, Ww, bw, Wout, bout);
    init_state_kernel<<<256, 256>>>(mem_init, read_init);

    dim3 thr(16, 16);
    dim3 grid_h(CC / 64, BB / 32);                 // (32, 4)
    dim3 grid_p((PDIM + 63) / 64, BB / 32);        // (17, 4)
    for (int t = 0; t < TT; t++) {
        gemm_h_kernel<<<grid_h, thr>>>(x, Wc, bc, t);
        gemm_p_kernel<<<grid_p, thr>>>(out, t);
        ntm_step_kernel<<<BB, 256, NN * MM * (int)sizeof(float)>>>();
    }
}

// round 3
// speedup vs baseline: 1.8041x; 1.8041x over previous
#include <cuda_runtime.h>
#include <math.h>

#define BB 128
#define TT 256
#define INDIM 512
#define CC 2048
#define NN 256
#define MM 128
#define OUTD 512
#define KH 640            // MM + INDIM
#define PR 134            // M+6
#define PWD 390           // 3M+6
#define PDIM 1036         // PR + PWD + OUTD
#define PDIMP 1088        // padded to 17*64 so every 64-col tile is in-bounds
#define EPSF 1e-8f

// -------- persistent device state (scratch) --------
__device__ float g_h[BB*CC];            // hidden (B, C)
__device__ float g_pp[2*BB*PDIMP];      // split-K partial projections
__device__ float g_r[BB*MM];            // read vector
__device__ float g_wr[BB*NN];           // read weights
__device__ float g_ww[BB*NN];           // write weights
__device__ float g_mem[BB*NN*MM];       // memory (B, N, M)
__device__ float g_Wall[CC*PDIMP];      // packed [Wr | Ww | Wout], zero-padded cols
__device__ float g_ball[PDIM];

// -------- helpers --------
__device__ __forceinline__ float sigmoidf_(float x) { return 1.f / (1.f + expf(-x)); }
__device__ __forceinline__ float softplusf_(float x) {
    return fmaxf(x, 0.f) + log1pf(expf(-fabsf(x)));
}

// -------- init kernels --------
__global__ void pack_w_kernel(const float* __restrict__ Wr, const float* __restrict__ br,
                              const float* __restrict__ Ww, const float* __restrict__ bw,
                              const float* __restrict__ Wout, const float* __restrict__ bout) {
    int gid = blockIdx.x * blockDim.x + threadIdx.x;
    int stride = gridDim.x * blockDim.x;
    for (int i = gid; i < PDIM; i += stride) {
        float v;
        if (i < PR) v = br[i];
        else if (i < PR + PWD) v = bw[i - PR];
        else v = bout[i - PR - PWD];
        g_ball[i] = v;
    }
    int total = CC * PDIMP;
    for (int idx = gid; idx < total; idx += stride) {
        int row = idx / PDIMP, col = idx % PDIMP;
        float v = 0.f;
        if (col < PR) v = Wr[row * PR + col];
        else if (col < PR + PWD) v = Ww[row * PWD + (col - PR)];
        else if (col < PDIM) v = Wout[row * OUTD + (col - PR - PWD)];
        g_Wall[idx] = v;
    }
}

__global__ void init_state_kernel(const float* __restrict__ mem_init,
                                  const float* __restrict__ read_init) {
    int gid = blockIdx.x * blockDim.x + threadIdx.x;
    int stride = gridDim.x * blockDim.x;
    const int memsz = BB * NN * MM;
    for (int i = gid; i < memsz; i += stride) g_mem[i] = mem_init[i % (NN * MM)];
    for (int i = gid; i < BB * NN; i += stride) { g_wr[i] = 1.f / NN; g_ww[i] = 1.f / NN; }
    for (int i = gid; i < BB * MM; i += stride) g_r[i] = read_init[i % MM];
}

// ============================================================================
// GEMM 1: h = tanh([r, x_t] @ Wc + bc)   (128 x 640) @ (640 x 2048)
// BM=32, BN=64, BK=32, 256 threads, 2x4 micro-tile, double-buffered smem.
// grid (32, 4) = 128 CTAs
// ============================================================================
__global__ void __launch_bounds__(256) gemm_h_kernel(const float* __restrict__ x,
                                                     const float* __restrict__ Wc,
                                                     const float* __restrict__ bc, int t) {
    __shared__ float As[2][32][34];   // [buf][k][m]
    __shared__ float Bs[2][32][68];   // [buf][k][n]
    const int tx = threadIdx.x, ty = threadIdx.y;
    const int tid = ty * 16 + tx;
    const int row0 = blockIdx.y * 32;
    const int col0 = blockIdx.x * 64;

    const int am = tid >> 3;          // 0..31
    const int akq = (tid & 7) << 2;   // 0..28
    const int bkr = tid >> 4;         // 0..15
    const int bn4 = (tid & 15) << 2;  // 0..60

    const int KT = KH / 32;  // 20
    float4 avr, bvr0, bvr1;

    {
        int b = row0 + am, k = akq;   // tile 0: k < 32 < MM -> from g_r
        avr = *(const float4*)(g_r + b * MM + k);
        bvr0 = *(const float4*)(Wc + bkr * CC + col0 + bn4);
        bvr1 = *(const float4*)(Wc + (bkr + 16) * CC + col0 + bn4);
        As[0][akq + 0][am] = avr.x; As[0][akq + 1][am] = avr.y;
        As[0][akq + 2][am] = avr.z; As[0][akq + 3][am] = avr.w;
        *(float4*)&Bs[0][bkr][bn4] = bvr0;
        *(float4*)&Bs[0][bkr + 16][bn4] = bvr1;
    }
    __syncthreads();

    float acc[2][4] = {{0.f,0.f,0.f,0.f},{0.f,0.f,0.f,0.f}};

    for (int kt = 0; kt < KT; kt++) {
        int cur = kt & 1;
        if (kt + 1 < KT) {
            int k0 = (kt + 1) * 32;
            int b = row0 + am, k = k0 + akq;
            if (k < MM) avr = *(const float4*)(g_r + b * MM + k);
            else        avr = *(const float4*)(x + ((long long)b * TT + t) * INDIM + (k - MM));
            bvr0 = *(const float4*)(Wc + (k0 + bkr) * CC + col0 + bn4);
            bvr1 = *(const float4*)(Wc + (k0 + bkr + 16) * CC + col0 + bn4);
        }
        #pragma unroll
        for (int kk = 0; kk < 32; kk++) {
            float2 a = *(const float2*)&As[cur][kk][ty * 2];
            float4 b = *(const float4*)&Bs[cur][kk][tx * 4];
            acc[0][0] += a.x * b.x; acc[0][1] += a.x * b.y; acc[0][2] += a.x * b.z; acc[0][3] += a.x * b.w;
            acc[1][0] += a.y * b.x; acc[1][1] += a.y * b.y; acc[1][2] += a.y * b.z; acc[1][3] += a.y * b.w;
        }
        if (kt + 1 < KT) {
            int nxt = cur ^ 1;
            As[nxt][akq + 0][am] = avr.x; As[nxt][akq + 1][am] = avr.y;
            As[nxt][akq + 2][am] = avr.z; As[nxt][akq + 3][am] = avr.w;
            *(float4*)&Bs[nxt][bkr][bn4] = bvr0;
            *(float4*)&Bs[nxt][bkr + 16][bn4] = bvr1;
            __syncthreads();
        }
    }

    #pragma unroll
    for (int i = 0; i < 2; i++) {
        int b = row0 + ty * 2 + i;
        int c = col0 + tx * 4;
        float4 bb = *(const float4*)(bc + c);
        float4 v;
        v.x = tanhf(acc[i][0] + bb.x);
        v.y = tanhf(acc[i][1] + bb.y);
        v.z = tanhf(acc[i][2] + bb.z);
        v.w = tanhf(acc[i][3] + bb.w);
        *(float4*)(g_h + b * CC + c) = v;
    }
}

// ============================================================================
// GEMM 2 (split-K=2): pp[ks] = h[:, ks*1024:(ks+1)*1024] @ Wall[ks*1024:...]
// BM=32, BN=64, BK=32, grid (17, 4, 2) = 136 CTAs. Columns padded to 1088,
// so every tile is fully in-bounds. No bias here.
// ============================================================================
__global__ void __launch_bounds__(256) gemm_p_kernel() {
    __shared__ float As[2][32][34];
    __shared__ float Bs[2][32][68];
    const int tx = threadIdx.x, ty = threadIdx.y;
    const int tid = ty * 16 + tx;
    const int row0 = blockIdx.y * 32;
    const int col0 = blockIdx.x * 64;
    const int kbase = blockIdx.z * 1024;

    const int am = tid >> 3;
    const int akq = (tid & 7) << 2;
    const int bkr = tid >> 4;
    const int bn4 = (tid & 15) << 2;

    const int KT = 1024 / 32;  // 32
    float4 avr, bvr0, bvr1;

    {
        int b = row0 + am;
        avr = *(const float4*)(g_h + b * CC + kbase + akq);
        bvr0 = *(const float4*)(g_Wall + (size_t)(kbase + bkr) * PDIMP + col0 + bn4);
        bvr1 = *(const float4*)(g_Wall + (size_t)(kbase + bkr + 16) * PDIMP + col0 + bn4);
        As[0][akq + 0][am] = avr.x; As[0][akq + 1][am] = avr.y;
        As[0][akq + 2][am] = avr.z; As[0][akq + 3][am] = avr.w;
        *(float4*)&Bs[0][bkr][bn4] = bvr0;
        *(float4*)&Bs[0][bkr + 16][bn4] = bvr1;
    }
    __syncthreads();

    float acc[2][4] = {{0.f,0.f,0.f,0.f},{0.f,0.f,0.f,0.f}};

    for (int kt = 0; kt < KT; kt++) {
        int cur = kt & 1;
        if (kt + 1 < KT) {
            int k0 = kbase + (kt + 1) * 32;
            int b = row0 + am;
            avr = *(const float4*)(g_h + b * CC + k0 + akq);
            bvr0 = *(const float4*)(g_Wall + (size_t)(k0 + bkr) * PDIMP + col0 + bn4);
            bvr1 = *(const float4*)(g_Wall + (size_t)(k0 + bkr + 16) * PDIMP + col0 + bn4);
        }
        #pragma unroll
        for (int kk = 0; kk < 32; kk++) {
            float2 a = *(const float2*)&As[cur][kk][ty * 2];
            float4 b = *(const float4*)&Bs[cur][kk][tx * 4];
            acc[0][0] += a.x * b.x; acc[0][1] += a.x * b.y; acc[0][2] += a.x * b.z; acc[0][3] += a.x * b.w;
            acc[1][0] += a.y * b.x; acc[1][1] += a.y * b.y; acc[1][2] += a.y * b.z; acc[1][3] += a.y * b.w;
        }
        if (kt + 1 < KT) {
            int nxt = cur ^ 1;
            As[nxt][akq + 0][am] = avr.x; As[nxt][akq + 1][am] = avr.y;
            As[nxt][akq + 2][am] = avr.z; As[nxt][akq + 3][am] = avr.w;
            *(float4*)&Bs[nxt][bkr][bn4] = bvr0;
            *(float4*)&Bs[nxt][bkr + 16][bn4] = bvr1;
            __syncthreads();
        }
    }

    float* pp = g_pp + (size_t)blockIdx.z * BB * PDIMP;
    #pragma unroll
    for (int i = 0; i < 2; i++) {
        int b = row0 + ty * 2 + i;
        int c = col0 + tx * 4;   // c < 1088 = PDIMP, always in-bounds
        float4 v = make_float4(acc[i][0], acc[i][1], acc[i][2], acc[i][3]);
        *(float4*)(pp + (size_t)b * PDIMP + c) = v;
    }
}

// ============================================================================
// fused NTM step: split-K reduce + bias, out write, addressing x2, read, update
// ============================================================================
__device__ __forceinline__ float warp_red_sum(float v) {
    #pragma unroll
    for (int o = 16; o; o >>= 1) v += __shfl_xor_sync(0xffffffffu, v, o);
    return v;
}
__device__ __forceinline__ float warp_red_max(float v) {
    #pragma unroll
    for (int o = 16; o; o >>= 1) v = fmaxf(v, __shfl_xor_sync(0xffffffffu, v, o));
    return v;
}
__device__ __forceinline__ float block_sum(float v, float* r8, int tid) {
    v = warp_red_sum(v);
    if ((tid & 31) == 0) r8[tid >> 5] = v;
    __syncthreads();
    float s = 0.f;
    #pragma unroll
    for (int i = 0; i < 8; i++) s += r8[i];
    return s;
}
__device__ __forceinline__ float block_max(float v, float* r8, int tid) {
    v = warp_red_max(v);
    if ((tid & 31) == 0) r8[tid >> 5] = v;
    __syncthreads();
    float s = r8[0];
    #pragma unroll
    for (int i = 1; i < 8; i++) s = fmaxf(s, r8[i]);
    return s;
}

// pp: smem ptr to 134 addressing params; gw: prev/next weights (global, per batch)
__device__ void address_fn(const float* __restrict__ pp, float* __restrict__ gw,
                           const float* __restrict__ s_mem,
                           float* __restrict__ s_w, float* __restrict__ r8x4, int tid) {
    float kv = (tid < MM) ? pp[tid] : 0.f;
    float knorm = sqrtf(block_sum(kv * kv, r8x4 + 0, tid));
    float beta  = softplusf_(pp[MM]);
    float gg    = sigmoidf_(pp[MM + 1]);
    float p2 = pp[MM + 2], p3 = pp[MM + 3], p4 = pp[MM + 4];
    float smax = fmaxf(p2, fmaxf(p3, p4));
    float e0 = expf(p2 - smax), e1 = expf(p3 - smax), e2 = expf(p4 - smax);
    float einv = 1.f / (e0 + e1 + e2);
    float s0 = e0 * einv, s1 = e1 * einv, s2 = e2 * einv;
    float gamma = 1.f + softplusf_(pp[MM + 5]);

    // cosine similarity for row n = tid (lane-skewed, conflict-free)
    float dot = 0.f, msq = 0.f;
    const int base = tid * MM;
    #pragma unroll 8
    for (int j = 0; j < MM; j++) {
        int m = (j + tid) & (MM - 1);
        float v = s_mem[base + m];
        dot += pp[m] * v;
        msq += v * v;
    }
    float sim = dot / (knorm * sqrtf(msq) + EPSF);

    float z = beta * sim;
    float zmax = block_max(z, r8x4 + 8, tid);
    float ez = expf(z - zmax);
    float zsum = block_sum(ez, r8x4 + 16, tid);
    float wc = ez / zsum;

    float wprev = gw[tid];
    float wg = gg * wc + (1.f - gg) * wprev;
    s_w[tid] = wg;
    __syncthreads();

    float wt = s_w[(tid + 1) & (NN - 1)] * s0 + wg * s1 + s_w[(tid + NN - 1) & (NN - 1)] * s2;
    float wp = powf(wt + EPSF, gamma);
    float wsum = block_sum(wp, r8x4 + 24, tid);   // internal sync orders s_w reads before writes below
    float wn = wp / wsum;
    s_w[tid] = wn;
    gw[tid] = wn;
    __syncthreads();
}

extern __shared__ float s_mem[];  // NN*MM floats (128 KB)

__global__ void __launch_bounds__(256) ntm_step_kernel(float* __restrict__ out, int t) {
    const int b = blockIdx.x;
    const int tid = threadIdx.x;

    __shared__ float s_p[PR + PWD];   // 524
    __shared__ float s_w[NN];
    __shared__ float s_red[NN];
    __shared__ float s_r8[32];
    __shared__ float s_e[MM];
    __shared__ float s_a[MM];

    const float* pp0 = g_pp + (size_t)b * PDIMP;
    const float* pp1 = g_pp + (size_t)BB * PDIMP + (size_t)b * PDIMP;

    // assemble p = part0 + part1 + bias for addressing columns
    for (int i = tid; i < PR + PWD; i += 256) s_p[i] = pp0[i] + pp1[i] + g_ball[i];
    // write output columns straight to d_out
    {
        int c = tid * 2;
        if (c < OUTD) {
            float v0 = pp0[PR + PWD + c] + pp1[PR + PWD + c] + g_ball[PR + PWD + c];
            float v1 = pp0[PR + PWD + c + 1] + pp1[PR + PWD + c + 1] + g_ball[PR + PWD + c + 1];
            float* o = out + ((long long)b * TT + t) * OUTD + c;
            o[0] = v0; o[1] = v1;
        }
    }
    // stage memory into smem (coalesced float4)
    {
        const float4* gm4 = reinterpret_cast<const float4*>(g_mem + (size_t)b * NN * MM);
        float4* sm4 = reinterpret_cast<float4*>(s_mem);
        #pragma unroll 4
        for (int i = tid; i < NN * MM / 4; i += 256) sm4[i] = gm4[i];
    }
    __syncthreads();
    if (tid < MM) {
        s_e[tid] = sigmoidf_(s_p[PR + PR + tid]);          // pw[134 + m]
        s_a[tid] = tanhf(s_p[PR + 2 * MM + 6 + tid]);      // pw[262 + m]
    }
    __syncthreads();

    // ---- read addressing (old mem) ----
    address_fn(s_p, g_wr + b * NN, s_mem, s_w, s_r8, tid);

    // ---- read vector: r[m] = sum_n w_r[n] * mem[n][m] ----
    {
        int m = tid & (MM - 1);
        int half = tid >> 7;
        float acc = 0.f;
        int n0 = half * 128;
        #pragma unroll 8
        for (int n = n0; n < n0 + 128; n++) acc += s_w[n] * s_mem[n * MM + m];
        s_red[tid] = acc;
        __syncthreads();
        if (tid < MM) g_r[b * MM + tid] = s_red[tid] + s_red[tid + 128];
        __syncthreads();
    }

    // ---- write addressing (old mem) ----
    address_fn(s_p + PR, g_ww + b * NN, s_mem, s_w, s_r8, tid);

    // ---- memory update ----
    {
        float4* gmo = reinterpret_cast<float4*>(g_mem + (size_t)b * NN * MM);
        const float4* sm4 = reinterpret_cast<const float4*>(s_mem);
        const float4* e4 = reinterpret_cast<const float4*>(s_e);
        const float4* a4 = reinterpret_cast<const float4*>(s_a);
        #pragma unroll 4
        for (int i = tid; i < NN * MM / 4; i += 256) {
            int n = i >> 5;
            int m4 = i & 31;
            float wwn = s_w[n];
            float4 old = sm4[i];
            float4 ev = e4[m4];
            float4 av = a4[m4];
            float4 r;
            r.x = old.x * (1.f - wwn * ev.x) + wwn * av.x;
            r.y = old.y * (1.f - wwn * ev.y) + wwn * av.y;
            r.z = old.z * (1.f - wwn * ev.z) + wwn * av.z;
            r.w = old.w * (1.f - wwn * ev.w) + wwn * av.w;
            gmo[i] = r;
        }
    }
}

// -------- launch --------
extern "C" void kernel_launch(void* const* d_in, const int* in_sizes, int n_in,
                              void* d_out, int out_size) {
    const float* x        = (const float*)d_in[0];
    const float* Wc       = (const float*)d_in[1];
    const float* bc       = (const float*)d_in[2];
    const float* Wout     = (const float*)d_in[3];
    const float* bout     = (const float*)d_in[4];
    const float* Wr       = (const float*)d_in[5];
    const float* br       = (const float*)d_in[6];
    const float* Ww       = (const float*)d_in[7];
    const float* bw       = (const float*)d_in[8];
    const float* mem_init = (const float*)d_in[9];
    const float* read_init= (const float*)d_in[10];
    float* out = (float*)d_out;
    (void)in_sizes; (void)n_in; (void)out_size;

    cudaFuncSetAttribute(ntm_step_kernel, cudaFuncAttributeMaxDynamicSharedMemorySize,
                         NN * MM * (int)sizeof(float));

    pack_w_kernel<<<256, 256>>>(Wr, br, Ww, bw, Wout, bout);
    init_state_kernel<<<256, 256>>>(mem_init, read_init);

    dim3 thr(16, 16);
    dim3 grid_h(CC / 64, BB / 32);        // (32, 4) = 128 CTAs
    dim3 grid_p(PDIMP / 64, BB / 32, 2);  // (17, 4, 2) = 136 CTAs
    for (int t = 0; t < TT; t++) {
        gemm_h_kernel<<<grid_h, thr>>>(x, Wc, bc, t);
        gemm_p_kernel<<<grid_p, thr>>>();
        ntm_step_kernel<<<BB, 256, NN * MM * (int)sizeof(float)>>>(out, t);
    }
}

// round 4
// speedup vs baseline: 2.1361x; 1.1840x over previous
#include <cuda_runtime.h>
#include <math.h>

#define BB 128
#define TT 256
#define INDIM 512
#define CC 2048
#define NN 256
#define MM 128
#define OUTD 512
#define PR 134            // M+6
#define PWD 390           // 3M+6
#define PDIM 1036         // PR + PWD + OUTD
#define PDIMP 1152        // padded to 9*128 col tiles
#define SKP 16            // split-K for gemm_p
#define EPSF 1e-8f

// -------- persistent device state (scratch) --------
__device__ float g_h[BB*CC];                 // hidden (B, C)
__device__ float g_pp[SKP*BB*PDIMP];         // split-K partial projections
__device__ float g_r[BB*MM];                 // read vector
__device__ float g_wr[BB*NN];                // read weights
__device__ float g_ww[BB*NN];                // write weights
__device__ float g_mem[BB*NN*MM];            // memory (B, N, M)
__device__ float g_Wall[CC*PDIMP];           // packed [Wr | Ww | Wout], zero-padded
__device__ float g_ball[PDIM];
__device__ float g_xproj[(size_t)BB*TT*CC];  // x @ Wc[M:,:] precomputed

typedef unsigned long long ull;

// packed fp32x2 FMA (Blackwell FFMA2)
#define FFMA2(d, a, b, c) \
    asm("fma.rn.f32x2 %0, %1, %2, %3;" : "=l"(d) : "l"(a), "l"(b), "l"(c))

__device__ __forceinline__ float2 ull2f2(ull v) {
    float2 r;
    r.x = __uint_as_float((unsigned)(v & 0xffffffffULL));
    r.y = __uint_as_float((unsigned)(v >> 32));
    return r;
}

__device__ __forceinline__ float sigmoidf_(float x) { return 1.f / (1.f + expf(-x)); }
__device__ __forceinline__ float softplusf_(float x) {
    return fmaxf(x, 0.f) + log1pf(expf(-fabsf(x)));
}

// -------- init kernels --------
__global__ void pack_w_kernel(const float* __restrict__ Wr, const float* __restrict__ br,
                              const float* __restrict__ Ww, const float* __restrict__ bw,
                              const float* __restrict__ Wout, const float* __restrict__ bout) {
    int gid = blockIdx.x * blockDim.x + threadIdx.x;
    int stride = gridDim.x * blockDim.x;
    for (int i = gid; i < PDIM; i += stride) {
        float v;
        if (i < PR) v = br[i];
        else if (i < PR + PWD) v = bw[i - PR];
        else v = bout[i - PR - PWD];
        g_ball[i] = v;
    }
    int total = CC * PDIMP;
    for (int idx = gid; idx < total; idx += stride) {
        int row = idx / PDIMP, col = idx % PDIMP;
        float v = 0.f;
        if (col < PR) v = Wr[row * PR + col];
        else if (col < PR + PWD) v = Ww[row * PWD + (col - PR)];
        else if (col < PDIM) v = Wout[row * OUTD + (col - PR - PWD)];
        g_Wall[idx] = v;
    }
}

__global__ void init_state_kernel(const float* __restrict__ mem_init,
                                  const float* __restrict__ read_init) {
    int gid = blockIdx.x * blockDim.x + threadIdx.x;
    int stride = gridDim.x * blockDim.x;
    const int memsz = BB * NN * MM;
    for (int i = gid; i < memsz; i += stride) g_mem[i] = mem_init[i % (NN * MM)];
    for (int i = gid; i < BB * NN; i += stride) { g_wr[i] = 1.f / NN; g_ww[i] = 1.f / NN; }
    for (int i = gid; i < BB * MM; i += stride) g_r[i] = read_init[i % MM];
}

// ============================================================================
// Shared tile geometry for the 64x128 f32x2 kernels:
//   BM=64, BN=128, BK=16, 256 threads (16x16), micro-tile 4 rows x 8 cols.
//   As2: A values duplicated in pairs {v,v} -> direct b64 operand loads.
// ============================================================================

// xproj = x[B*T, 512] @ Wc[128:640, :]    grid (16, 512)
__global__ void __launch_bounds__(256, 2) xproj_kernel(const float* __restrict__ x,
                                                       const float* __restrict__ Wc) {
    __shared__ __align__(16) float As2[2][16][132];
    __shared__ __align__(16) float Bs[2][16][132];
    const int tx = threadIdx.x, ty = threadIdx.y;
    const int tid = ty * 16 + tx;
    const long long row0 = (long long)blockIdx.y * 64;
    const int col0 = blockIdx.x * 128;

    const int am = tid >> 2;          // 0..63
    const int akq = (tid & 3) << 2;   // 0,4,8,12
    const int bkr = tid >> 5;         // 0..7
    const int bn4 = (tid & 31) << 2;  // 0..124

    const int KT = INDIM / 16;  // 32
    float4 avr, bvr0, bvr1;

    {
        avr = *(const float4*)(x + (row0 + am) * INDIM + akq);
        bvr0 = *(const float4*)(Wc + (size_t)(MM + bkr) * CC + col0 + bn4);
        bvr1 = *(const float4*)(Wc + (size_t)(MM + bkr + 8) * CC + col0 + bn4);
        *(float2*)&As2[0][akq + 0][2 * am] = make_float2(avr.x, avr.x);
        *(float2*)&As2[0][akq + 1][2 * am] = make_float2(avr.y, avr.y);
        *(float2*)&As2[0][akq + 2][2 * am] = make_float2(avr.z, avr.z);
        *(float2*)&As2[0][akq + 3][2 * am] = make_float2(avr.w, avr.w);
        *(float4*)&Bs[0][bkr][bn4] = bvr0;
        *(float4*)&Bs[0][bkr + 8][bn4] = bvr1;
    }
    __syncthreads();

    ull acc[4][4] = {{0,0,0,0},{0,0,0,0},{0,0,0,0},{0,0,0,0}};

    for (int kt = 0; kt < KT; kt++) {
        int cur = kt & 1;
        if (kt + 1 < KT) {
            int k0 = (kt + 1) * 16;
            avr = *(const float4*)(x + (row0 + am) * INDIM + k0 + akq);
            bvr0 = *(const float4*)(Wc + (size_t)(MM + k0 + bkr) * CC + col0 + bn4);
            bvr1 = *(const float4*)(Wc + (size_t)(MM + k0 + bkr + 8) * CC + col0 + bn4);
        }
        #pragma unroll
        for (int kk = 0; kk < 16; kk++) {
            ulonglong2 a01 = *(const ulonglong2*)&As2[cur][kk][ty * 8];
            ulonglong2 a23 = *(const ulonglong2*)&As2[cur][kk][ty * 8 + 4];
            ulonglong2 b01 = *(const ulonglong2*)&Bs[cur][kk][tx * 8];
            ulonglong2 b23 = *(const ulonglong2*)&Bs[cur][kk][tx * 8 + 4];
            ull av[4] = {a01.x, a01.y, a23.x, a23.y};
            ull bv[4] = {b01.x, b01.y, b23.x, b23.y};
            #pragma unroll
            for (int i = 0; i < 4; i++)
                #pragma unroll
                for (int j = 0; j < 4; j++)
                    FFMA2(acc[i][j], av[i], bv[j], acc[i][j]);
        }
        if (kt + 1 < KT) {
            int nxt = cur ^ 1;
            *(float2*)&As2[nxt][akq + 0][2 * am] = make_float2(avr.x, avr.x);
            *(float2*)&As2[nxt][akq + 1][2 * am] = make_float2(avr.y, avr.y);
            *(float2*)&As2[nxt][akq + 2][2 * am] = make_float2(avr.z, avr.z);
            *(float2*)&As2[nxt][akq + 3][2 * am] = make_float2(avr.w, avr.w);
            *(float4*)&Bs[nxt][bkr][bn4] = bvr0;
            *(float4*)&Bs[nxt][bkr + 8][bn4] = bvr1;
            __syncthreads();
        }
    }

    #pragma unroll
    for (int i = 0; i < 4; i++) {
        long long m = row0 + ty * 4 + i;
        int c = col0 + tx * 8;
        float2 p0 = ull2f2(acc[i][0]), p1 = ull2f2(acc[i][1]);
        float2 p2 = ull2f2(acc[i][2]), p3 = ull2f2(acc[i][3]);
        *(float4*)(g_xproj + m * CC + c)     = make_float4(p0.x, p0.y, p1.x, p1.y);
        *(float4*)(g_xproj + m * CC + c + 4) = make_float4(p2.x, p2.y, p3.x, p3.y);
    }
}

// gemm_p (split-K=16): pp[z] = h[:, z*128:(z+1)*128] @ Wall[z*128:...]
// grid (9, 2, 16) = 288 CTAs
__global__ void __launch_bounds__(256, 2) gemm_p_kernel() {
    __shared__ __align__(16) float As2[2][16][132];
    __shared__ __align__(16) float Bs[2][16][132];
    const int tx = threadIdx.x, ty = threadIdx.y;
    const int tid = ty * 16 + tx;
    const int row0 = blockIdx.y * 64;
    const int col0 = blockIdx.x * 128;
    const int kbase = blockIdx.z * (CC / SKP);   // *128

    const int am = tid >> 2;
    const int akq = (tid & 3) << 2;
    const int bkr = tid >> 5;
    const int bn4 = (tid & 31) << 2;

    const int KT = (CC / SKP) / 16;  // 8
    float4 avr, bvr0, bvr1;

    {
        avr = *(const float4*)(g_h + (size_t)(row0 + am) * CC + kbase + akq);
        bvr0 = *(const float4*)(g_Wall + (size_t)(kbase + bkr) * PDIMP + col0 + bn4);
        bvr1 = *(const float4*)(g_Wall + (size_t)(kbase + bkr + 8) * PDIMP + col0 + bn4);
        *(float2*)&As2[0][akq + 0][2 * am] = make_float2(avr.x, avr.x);
        *(float2*)&As2[0][akq + 1][2 * am] = make_float2(avr.y, avr.y);
        *(float2*)&As2[0][akq + 2][2 * am] = make_float2(avr.z, avr.z);
        *(float2*)&As2[0][akq + 3][2 * am] = make_float2(avr.w, avr.w);
        *(float4*)&Bs[0][bkr][bn4] = bvr0;
        *(float4*)&Bs[0][bkr + 8][bn4] = bvr1;
    }
    __syncthreads();

    ull acc[4][4] = {{0,0,0,0},{0,0,0,0},{0,0,0,0},{0,0,0,0}};

    for (int kt = 0; kt < KT; kt++) {
        int cur = kt & 1;
        if (kt + 1 < KT) {
            int k0 = kbase + (kt + 1) * 16;
            avr = *(const float4*)(g_h + (size_t)(row0 + am) * CC + k0 + akq);
            bvr0 = *(const float4*)(g_Wall + (size_t)(k0 + bkr) * PDIMP + col0 + bn4);
            bvr1 = *(const float4*)(g_Wall + (size_t)(k0 + bkr + 8) * PDIMP + col0 + bn4);
        }
        #pragma unroll
        for (int kk = 0; kk < 16; kk++) {
            ulonglong2 a01 = *(const ulonglong2*)&As2[cur][kk][ty * 8];
            ulonglong2 a23 = *(const ulonglong2*)&As2[cur][kk][ty * 8 + 4];
            ulonglong2 b01 = *(const ulonglong2*)&Bs[cur][kk][tx * 8];
            ulonglong2 b23 = *(const ulonglong2*)&Bs[cur][kk][tx * 8 + 4];
            ull av[4] = {a01.x, a01.y, a23.x, a23.y};
            ull bv[4] = {b01.x, b01.y, b23.x, b23.y};
            #pragma unroll
            for (int i = 0; i < 4; i++)
                #pragma unroll
                for (int j = 0; j < 4; j++)
                    FFMA2(acc[i][j], av[i], bv[j], acc[i][j]);
        }
        if (kt + 1 < KT) {
            int nxt = cur ^ 1;
            *(float2*)&As2[nxt][akq + 0][2 * am] = make_float2(avr.x, avr.x);
            *(float2*)&As2[nxt][akq + 1][2 * am] = make_float2(avr.y, avr.y);
            *(float2*)&As2[nxt][akq + 2][2 * am] = make_float2(avr.z, avr.z);
            *(float2*)&As2[nxt][akq + 3][2 * am] = make_float2(avr.w, avr.w);
            *(float4*)&Bs[nxt][bkr][bn4] = bvr0;
            *(float4*)&Bs[nxt][bkr + 8][bn4] = bvr1;
            __syncthreads();
        }
    }

    float* pp = g_pp + (size_t)blockIdx.z * BB * PDIMP;
    #pragma unroll
    for (int i = 0; i < 4; i++) {
        int m = row0 + ty * 4 + i;
        int c = col0 + tx * 8;
        float2 p0 = ull2f2(acc[i][0]), p1 = ull2f2(acc[i][1]);
        float2 p2 = ull2f2(acc[i][2]), p3 = ull2f2(acc[i][3]);
        *(float4*)(pp + (size_t)m * PDIMP + c)     = make_float4(p0.x, p0.y, p1.x, p1.y);
        *(float4*)(pp + (size_t)m * PDIMP + c + 4) = make_float4(p2.x, p2.y, p3.x, p3.y);
    }
}

// gemm_hr: h = tanh(r @ Wc[0:128,:] + xproj[:,t,:] + bc)
// BM=16, BN=128, BK=16, grid (16, 8) = 128 CTAs, micro 1x8
__global__ void __launch_bounds__(256) gemm_hr_kernel(const float* __restrict__ Wc,
                                                      const float* __restrict__ bc, int t) {
    __shared__ __align__(16) float As2[2][16][36];
    __shared__ __align__(16) float Bs[2][16][132];
    const int tx = threadIdx.x, ty = threadIdx.y;
    const int tid = ty * 16 + tx;
    const int row0 = blockIdx.y * 16;
    const int col0 = blockIdx.x * 128;

    const int am = tid >> 4;        // 0..15
    const int akk = tid & 15;       // 0..15
    const int bkr = tid >> 5;
    const int bn4 = (tid & 31) << 2;

    const int KT = MM / 16;  // 8
    float avr;
    float4 bvr0, bvr1;

    {
        avr = g_r[(row0 + am) * MM + akk];
        bvr0 = *(const float4*)(Wc + (size_t)bkr * CC + col0 + bn4);
        bvr1 = *(const float4*)(Wc + (size_t)(bkr + 8) * CC + col0 + bn4);
        *(float2*)&As2[0][akk][2 * am] = make_float2(avr, avr);
        *(float4*)&Bs[0][bkr][bn4] = bvr0;
        *(float4*)&Bs[0][bkr + 8][bn4] = bvr1;
    }
    __syncthreads();

    ull acc[4] = {0, 0, 0, 0};

    for (int kt = 0; kt < KT; kt++) {
        int cur = kt & 1;
        if (kt + 1 < KT) {
            int k0 = (kt + 1) * 16;
            avr = g_r[(row0 + am) * MM + k0 + akk];
            bvr0 = *(const float4*)(Wc + (size_t)(k0 + bkr) * CC + col0 + bn4);
            bvr1 = *(const float4*)(Wc + (size_t)(k0 + bkr + 8) * CC + col0 + bn4);
        }
        #pragma unroll
        for (int kk = 0; kk < 16; kk++) {
            ull a2 = *(const ull*)&As2[cur][kk][ty * 2];
            ulonglong2 b01 = *(const ulonglong2*)&Bs[cur][kk][tx * 8];
            ulonglong2 b23 = *(const ulonglong2*)&Bs[cur][kk][tx * 8 + 4];
            FFMA2(acc[0], a2, b01.x, acc[0]);
            FFMA2(acc[1], a2, b01.y, acc[1]);
            FFMA2(acc[2], a2, b23.x, acc[2]);
            FFMA2(acc[3], a2, b23.y, acc[3]);
        }
        if (kt + 1 < KT) {
            int nxt = cur ^ 1;
            *(float2*)&As2[nxt][akk][2 * am] = make_float2(avr, avr);
            *(float4*)&Bs[nxt][bkr][bn4] = bvr0;
            *(float4*)&Bs[nxt][bkr + 8][bn4] = bvr1;
            __syncthreads();
        }
    }

    {
        int m = row0 + ty;
        int c = col0 + tx * 8;
        const float* xp = g_xproj + ((size_t)m * TT + t) * CC + c;
        float4 x0 = *(const float4*)(xp);
        float4 x1 = *(const float4*)(xp + 4);
        float4 b0 = *(const float4*)(bc + c);
        float4 b1 = *(const float4*)(bc + c + 4);
        float2 p0 = ull2f2(acc[0]), p1 = ull2f2(acc[1]);
        float2 p2 = ull2f2(acc[2]), p3 = ull2f2(acc[3]);
        float4 v0, v1;
        v0.x = tanhf(p0.x + x0.x + b0.x);
        v0.y = tanhf(p0.y + x0.y + b0.y);
        v0.z = tanhf(p1.x + x0.z + b0.z);
        v0.w = tanhf(p1.y + x0.w + b0.w);
        v1.x = tanhf(p2.x + x1.x + b1.x);
        v1.y = tanhf(p2.y + x1.y + b1.y);
        v1.z = tanhf(p3.x + x1.z + b1.z);
        v1.w = tanhf(p3.y + x1.w + b1.w);
        *(float4*)(g_h + (size_t)m * CC + c)     = v0;
        *(float4*)(g_h + (size_t)m * CC + c + 4) = v1;
    }
}

// ============================================================================
// fused NTM step: split-K reduce + bias, out write, addressing x2, read, update
// ============================================================================
__device__ __forceinline__ float warp_red_sum(float v) {
    #pragma unroll
    for (int o = 16; o; o >>= 1) v += __shfl_xor_sync(0xffffffffu, v, o);
    return v;
}
__device__ __forceinline__ float warp_red_max(float v) {
    #pragma unroll
    for (int o = 16; o; o >>= 1) v = fmaxf(v, __shfl_xor_sync(0xffffffffu, v, o));
    return v;
}
__device__ __forceinline__ float block_sum(float v, float* r8, int tid) {
    v = warp_red_sum(v);
    if ((tid & 31) == 0) r8[tid >> 5] = v;
    __syncthreads();
    float s = 0.f;
    #pragma unroll
    for (int i = 0; i < 8; i++) s += r8[i];
    return s;
}
__device__ __forceinline__ float block_max(float v, float* r8, int tid) {
    v = warp_red_max(v);
    if ((tid & 31) == 0) r8[tid >> 5] = v;
    __syncthreads();
    float s = r8[0];
    #pragma unroll
    for (int i = 1; i < 8; i++) s = fmaxf(s, r8[i]);
    return s;
}

__device__ void address_fn(const float* __restrict__ pp, float* __restrict__ gw,
                           const float* __restrict__ s_mem,
                           float* __restrict__ s_w, float* __restrict__ r8x4, int tid) {
    float kv = (tid < MM) ? pp[tid] : 0.f;
    float knorm = sqrtf(block_sum(kv * kv, r8x4 + 0, tid));
    float beta  = softplusf_(pp[MM]);
    float gg    = sigmoidf_(pp[MM + 1]);
    float p2 = pp[MM + 2], p3 = pp[MM + 3], p4 = pp[MM + 4];
    float smax = fmaxf(p2, fmaxf(p3, p4));
    float e0 = expf(p2 - smax), e1 = expf(p3 - smax), e2 = expf(p4 - smax);
    float einv = 1.f / (e0 + e1 + e2);
    float s0 = e0 * einv, s1 = e1 * einv, s2 = e2 * einv;
    float gamma = 1.f + softplusf_(pp[MM + 5]);

    float dot = 0.f, msq = 0.f;
    const int base = tid * MM;
    #pragma unroll 8
    for (int j = 0; j < MM; j++) {
        int m = (j + tid) & (MM - 1);
        float v = s_mem[base + m];
        dot += pp[m] * v;
        msq += v * v;
    }
    float sim = dot / (knorm * sqrtf(msq) + EPSF);

    float z = beta * sim;
    float zmax = block_max(z, r8x4 + 8, tid);
    float ez = expf(z - zmax);
    float zsum = block_sum(ez, r8x4 + 16, tid);
    float wc = ez / zsum;

    float wprev = gw[tid];
    float wg = gg * wc + (1.f - gg) * wprev;
    s_w[tid] = wg;
    __syncthreads();

    float wt = s_w[(tid + 1) & (NN - 1)] * s0 + wg * s1 + s_w[(tid + NN - 1) & (NN - 1)] * s2;
    float wp = powf(wt + EPSF, gamma);
    float wsum = block_sum(wp, r8x4 + 24, tid);
    float wn = wp / wsum;
    s_w[tid] = wn;
    gw[tid] = wn;
    __syncthreads();
}

extern __shared__ float s_mem[];  // NN*MM floats (128 KB)

__global__ void __launch_bounds__(256) ntm_step_kernel(float* __restrict__ out, int t) {
    const int b = blockIdx.x;
    const int tid = threadIdx.x;

    __shared__ float s_p[PR + PWD];
    __shared__ float s_w[NN];
    __shared__ float s_red[NN];
    __shared__ float s_r8[32];
    __shared__ float s_e[MM];
    __shared__ float s_a[MM];

    // reduce split-K partials + bias for addressing columns
    for (int i = tid; i < PR + PWD; i += 256) {
        float s = g_ball[i];
        #pragma unroll
        for (int ks = 0; ks < SKP; ks++)
            s += g_pp[(size_t)ks * BB * PDIMP + (size_t)b * PDIMP + i];
        s_p[i] = s;
    }
    // output columns straight to d_out
    {
        int c = tid * 2;
        if (c < OUTD) {
            float v0 = g_ball[PR + PWD + c];
            float v1 = g_ball[PR + PWD + c + 1];
            #pragma unroll
            for (int ks = 0; ks < SKP; ks++) {
                const float* pp = g_pp + (size_t)ks * BB * PDIMP + (size_t)b * PDIMP + PR + PWD + c;
                v0 += pp[0]; v1 += pp[1];
            }
            float* o = out + ((long long)b * TT + t) * OUTD + c;
            o[0] = v0; o[1] = v1;
        }
    }
    // stage memory into smem
    {
        const float4* gm4 = reinterpret_cast<const float4*>(g_mem + (size_t)b * NN * MM);
        float4* sm4 = reinterpret_cast<float4*>(s_mem);
        #pragma unroll 4
        for (int i = tid; i < NN * MM / 4; i += 256) sm4[i] = gm4[i];
    }
    __syncthreads();
    if (tid < MM) {
        s_e[tid] = sigmoidf_(s_p[PR + PR + tid]);
        s_a[tid] = tanhf(s_p[PR + 2 * MM + 6 + tid]);
    }
    __syncthreads();

    // read addressing (old mem)
    address_fn(s_p, g_wr + b * NN, s_mem, s_w, s_r8, tid);

    // read vector
    {
        int m = tid & (MM - 1);
        int half = tid >> 7;
        float acc = 0.f;
        int n0 = half * 128;
        #pragma unroll 8
        for (int n = n0; n < n0 + 128; n++) acc += s_w[n] * s_mem[n * MM + m];
        s_red[tid] = acc;
        __syncthreads();
        if (tid < MM) g_r[b * MM + tid] = s_red[tid] + s_red[tid + 128];
        __syncthreads();
    }

    // write addressing (old mem)
    address_fn(s_p + PR, g_ww + b * NN, s_mem, s_w, s_r8, tid);

    // memory update
    {
        float4* gmo = reinterpret_cast<float4*>(g_mem + (size_t)b * NN * MM);
        const float4* sm4 = reinterpret_cast<const float4*>(s_mem);
        const float4* e4 = reinterpret_cast<const float4*>(s_e);
        const float4* a4 = reinterpret_cast<const float4*>(s_a);
        #pragma unroll 4
        for (int i = tid; i < NN * MM / 4; i += 256) {
            int n = i >> 5;
            int m4 = i & 31;
            float wwn = s_w[n];
            float4 old = sm4[i];
            float4 ev = e4[m4];
            float4 av = a4[m4];
            float4 r;
            r.x = old.x * (1.f - wwn * ev.x) + wwn * av.x;
            r.y = old.y * (1.f - wwn * ev.y) + wwn * av.y;
            r.z = old.z * (1.f - wwn * ev.z) + wwn * av.z;
            r.w = old.w * (1.f - wwn * ev.w) + wwn * av.w;
            gmo[i] = r;
        }
    }
}

// -------- launch --------
extern "C" void kernel_launch(void* const* d_in, const int* in_sizes, int n_in,
                              void* d_out, int out_size) {
    const float* x        = (const float*)d_in[0];
    const float* Wc       = (const float*)d_in[1];
    const float* bc       = (const float*)d_in[2];
    const float* Wout     = (const float*)d_in[3];
    const float* bout     = (const float*)d_in[4];
    const float* Wr       = (const float*)d_in[5];
    const float* br       = (const float*)d_in[6];
    const float* Ww       = (const float*)d_in[7];
    const float* bw       = (const float*)d_in[8];
    const float* mem_init = (const float*)d_in[9];
    const float* read_init= (const float*)d_in[10];
    float* out = (float*)d_out;
    (void)in_sizes; (void)n_in; (void)out_size;

    cudaFuncSetAttribute(ntm_step_kernel, cudaFuncAttributeMaxDynamicSharedMemorySize,
                         NN * MM * (int)sizeof(float));

    pack_w_kernel<<<256, 256>>>(Wr, br, Ww, bw, Wout, bout);
    init_state_kernel<<<256, 256>>>(mem_init, read_init);

    dim3 thr(16, 16);
    dim3 grid_x(CC / 128, (BB * TT) / 64);   // (16, 512)
    xproj_kernel<<<grid_x, thr>>>(x, Wc);

    dim3 grid_h(CC / 128, BB / 16);          // (16, 8) = 128 CTAs
    dim3 grid_p(PDIMP / 128, BB / 64, SKP);  // (9, 2, 16) = 288 CTAs
    for (int t = 0; t < TT; t++) {
        gemm_hr_kernel<<<grid_h, thr>>>(Wc, bc, t);
        gemm_p_kernel<<<grid_p, thr>>>();
        ntm_step_kernel<<<BB, 256, NN * MM * (int)sizeof(float)>>>(out, t);
    }
}

// round 5
// speedup vs baseline: 2.2420x; 1.0496x over previous
#include <cuda_runtime.h>
#include <math.h>

#define BB 128
#define TT 256
#define INDIM 512
#define CC 2048
#define NN 256
#define MM 128
#define OUTD 512
#define PR 134            // M+6
#define PWD 390           // 3M+6
#define PDIM 1036         // PR + PWD + OUTD
#define PDIMP 1152        // padded to 9*128 col tiles
#define SK 8              // split-K for gemm_p phase (18 tiles * 8 = 144 jobs)
#define NCTA 144
#define EPSF 1e-8f

typedef unsigned long long ull;

// -------- persistent device state (scratch; __device__ globals are the sanctioned scratch) ----
__device__ float g_h[BB*CC];                 // hidden (B, C)
__device__ float g_pp[SK*BB*PDIMP];          // split-K partial projections
__device__ float g_r[BB*MM];                 // read vector
__device__ float g_Wall[CC*PDIMP];           // packed [Wr | Ww | Wout], zero-padded
__device__ float g_ball[PDIM];
__device__ float g_xproj[(size_t)TT*BB*CC];  // x @ Wc[M:,:], laid out [t][b][c]
__device__ unsigned g_bar_cnt;               // grid barrier state (returns to 0 each barrier)
__device__ unsigned g_bar_gen;

// packed fp32x2 FMA (Blackwell FFMA2)
#define FFMA2(d, a, b, c) \
    asm("fma.rn.f32x2 %0, %1, %2, %3;" : "=l"(d) : "l"(a), "l"(b), "l"(c))

__device__ __forceinline__ float2 ull2f2(ull v) {
    float2 r;
    r.x = __uint_as_float((unsigned)(v & 0xffffffffULL));
    r.y = __uint_as_float((unsigned)(v >> 32));
    return r;
}

__device__ __forceinline__ float sigmoidf_(float x) { return 1.f / (1.f + expf(-x)); }
__device__ __forceinline__ float softplusf_(float x) {
    return fmaxf(x, 0.f) + log1pf(expf(-fabsf(x)));
}

// -------- software grid barrier (all NCTA CTAs resident: 144 CTAs, 1/SM) --------
__device__ __forceinline__ void grid_barrier() {
    __syncthreads();
    if (threadIdx.x == 0) {
        __threadfence();
        unsigned gen;
        asm volatile("ld.acquire.gpu.u32 %0, [%1];" : "=r"(gen) : "l"(&g_bar_gen) : "memory");
        if (atomicAdd(&g_bar_cnt, 1u) == NCTA - 1) {
            atomicExch(&g_bar_cnt, 0u);
            __threadfence();
            atomicExch(&g_bar_gen, gen + 1u);
        } else {
            unsigned cur;
            do {
                __nanosleep(32);
                asm volatile("ld.acquire.gpu.u32 %0, [%1];" : "=r"(cur) : "l"(&g_bar_gen) : "memory");
            } while (cur == gen);
        }
    }
    __syncthreads();
}

// -------- init: pack projection weights --------
__global__ void pack_w_kernel(const float* __restrict__ Wr, const float* __restrict__ br,
                              const float* __restrict__ Ww, const float* __restrict__ bw,
                              const float* __restrict__ Wout, const float* __restrict__ bout) {
    int gid = blockIdx.x * blockDim.x + threadIdx.x;
    int stride = gridDim.x * blockDim.x;
    for (int i = gid; i < PDIM; i += stride) {
        float v;
        if (i < PR) v = br[i];
        else if (i < PR + PWD) v = bw[i - PR];
        else v = bout[i - PR - PWD];
        g_ball[i] = v;
    }
    int total = CC * PDIMP;
    for (int idx = gid; idx < total; idx += stride) {
        int row = idx / PDIMP, col = idx % PDIMP;
        float v = 0.f;
        if (col < PR) v = Wr[row * PR + col];
        else if (col < PR + PWD) v = Ww[row * PWD + (col - PR)];
        else if (col < PDIM) v = Wout[row * OUTD + (col - PR - PWD)];
        g_Wall[idx] = v;
    }
}

// -------- xproj = x[B*T, 512] @ Wc[128:640, :]  -> stored [t][b][c] --------
// BM=64, BN=128, BK=16, 256 threads, 4x8 micro-tile (f32x2), grid (16, 512)
__global__ void __launch_bounds__(256, 2) xproj_kernel(const float* __restrict__ x,
                                                       const float* __restrict__ Wc) {
    __shared__ __align__(16) float As2[2][16][132];
    __shared__ __align__(16) float Bs[2][16][132];
    const int tx = threadIdx.x, ty = threadIdx.y;
    const int tid = ty * 16 + tx;
    const long long row0 = (long long)blockIdx.y * 64;
    const int col0 = blockIdx.x * 128;

    const int am = tid >> 2;
    const int akq = (tid & 3) << 2;
    const int bkr = tid >> 5;
    const int bn4 = (tid & 31) << 2;

    const int KT = INDIM / 16;  // 32
    float4 avr, bvr0, bvr1;

    {
        avr = *(const float4*)(x + (row0 + am) * INDIM + akq);
        bvr0 = *(const float4*)(Wc + (size_t)(MM + bkr) * CC + col0 + bn4);
        bvr1 = *(const float4*)(Wc + (size_t)(MM + bkr + 8) * CC + col0 + bn4);
        *(float2*)&As2[0][akq + 0][2 * am] = make_float2(avr.x, avr.x);
        *(float2*)&As2[0][akq + 1][2 * am] = make_float2(avr.y, avr.y);
        *(float2*)&As2[0][akq + 2][2 * am] = make_float2(avr.z, avr.z);
        *(float2*)&As2[0][akq + 3][2 * am] = make_float2(avr.w, avr.w);
        *(float4*)&Bs[0][bkr][bn4] = bvr0;
        *(float4*)&Bs[0][bkr + 8][bn4] = bvr1;
    }
    __syncthreads();

    ull acc[4][4] = {{0,0,0,0},{0,0,0,0},{0,0,0,0},{0,0,0,0}};

    for (int kt = 0; kt < KT; kt++) {
        int cur = kt & 1;
        if (kt + 1 < KT) {
            int k0 = (kt + 1) * 16;
            avr = *(const float4*)(x + (row0 + am) * INDIM + k0 + akq);
            bvr0 = *(const float4*)(Wc + (size_t)(MM + k0 + bkr) * CC + col0 + bn4);
            bvr1 = *(const float4*)(Wc + (size_t)(MM + k0 + bkr + 8) * CC + col0 + bn4);
        }
        #pragma unroll
        for (int kk = 0; kk < 16; kk++) {
            ulonglong2 a01 = *(const ulonglong2*)&As2[cur][kk][ty * 8];
            ulonglong2 a23 = *(const ulonglong2*)&As2[cur][kk][ty * 8 + 4];
            ulonglong2 b01 = *(const ulonglong2*)&Bs[cur][kk][tx * 8];
            ulonglong2 b23 = *(const ulonglong2*)&Bs[cur][kk][tx * 8 + 4];
            ull av[4] = {a01.x, a01.y, a23.x, a23.y};
            ull bv[4] = {b01.x, b01.y, b23.x, b23.y};
            #pragma unroll
            for (int i = 0; i < 4; i++)
                #pragma unroll
                for (int j = 0; j < 4; j++)
                    FFMA2(acc[i][j], av[i], bv[j], acc[i][j]);
        }
        if (kt + 1 < KT) {
            int nxt = cur ^ 1;
            *(float2*)&As2[nxt][akq + 0][2 * am] = make_float2(avr.x, avr.x);
            *(float2*)&As2[nxt][akq + 1][2 * am] = make_float2(avr.y, avr.y);
            *(float2*)&As2[nxt][akq + 2][2 * am] = make_float2(avr.z, avr.z);
            *(float2*)&As2[nxt][akq + 3][2 * am] = make_float2(avr.w, avr.w);
            *(float4*)&Bs[nxt][bkr][bn4] = bvr0;
            *(float4*)&Bs[nxt][bkr + 8][bn4] = bvr1;
            __syncthreads();
        }
    }

    #pragma unroll
    for (int i = 0; i < 4; i++) {
        long long rid = row0 + ty * 4 + i;     // rid = b*TT + t
        int bb = (int)(rid >> 8);              // TT = 256
        int tt = (int)(rid & 255);
        int c = col0 + tx * 8;
        float* dst = g_xproj + ((size_t)tt * BB + bb) * CC + c;
        float2 p0 = ull2f2(acc[i][0]), p1 = ull2f2(acc[i][1]);
        float2 p2 = ull2f2(acc[i][2]), p3 = ull2f2(acc[i][3]);
        *(float4*)(dst)     = make_float4(p0.x, p0.y, p1.x, p1.y);
        *(float4*)(dst + 4) = make_float4(p2.x, p2.y, p3.x, p3.y);
    }
}

// -------- block reductions --------
__device__ __forceinline__ float warp_red_sum(float v) {
    #pragma unroll
    for (int o = 16; o; o >>= 1) v += __shfl_xor_sync(0xffffffffu, v, o);
    return v;
}
__device__ __forceinline__ float warp_red_max(float v) {
    #pragma unroll
    for (int o = 16; o; o >>= 1) v = fmaxf(v, __shfl_xor_sync(0xffffffffu, v, o));
    return v;
}
__device__ __forceinline__ float block_sum(float v, float* r8, int tid) {
    v = warp_red_sum(v);
    if ((tid & 31) == 0) r8[tid >> 5] = v;
    __syncthreads();
    float s = 0.f;
    #pragma unroll
    for (int i = 0; i < 8; i++) s += r8[i];
    return s;
}
__device__ __forceinline__ float block_max(float v, float* r8, int tid) {
    v = warp_red_max(v);
    if ((tid & 31) == 0) r8[tid >> 5] = v;
    __syncthreads();
    float s = r8[0];
    #pragma unroll
    for (int i = 1; i < 8; i++) s = fmaxf(s, r8[i]);
    return s;
}

// NTM addressing; sw: prev/next weights in SMEM (persistent per CTA)
__device__ void address_fn(const float* __restrict__ pp, float* __restrict__ sw_state,
                           const float* __restrict__ s_mem,
                           float* __restrict__ s_w, float* __restrict__ r8x4, int tid) {
    float kv = (tid < MM) ? pp[tid] : 0.f;
    float knorm = sqrtf(block_sum(kv * kv, r8x4 + 0, tid));
    float beta  = softplusf_(pp[MM]);
    float gg    = sigmoidf_(pp[MM + 1]);
    float p2 = pp[MM + 2], p3 = pp[MM + 3], p4 = pp[MM + 4];
    float smax = fmaxf(p2, fmaxf(p3, p4));
    float e0 = expf(p2 - smax), e1 = expf(p3 - smax), e2 = expf(p4 - smax);
    float einv = 1.f / (e0 + e1 + e2);
    float s0 = e0 * einv, s1 = e1 * einv, s2 = e2 * einv;
    float gamma = 1.f + softplusf_(pp[MM + 5]);

    // cosine similarity, row n = tid (lane-skewed, conflict-free)
    float dot = 0.f, msq = 0.f;
    const int base = tid * MM;
    #pragma unroll 8
    for (int j = 0; j < MM; j++) {
        int m = (j + tid) & (MM - 1);
        float v = s_mem[base + m];
        dot += pp[m] * v;
        msq += v * v;
    }
    float sim = dot / (knorm * sqrtf(msq) + EPSF);

    float z = beta * sim;
    float zmax = block_max(z, r8x4 + 8, tid);
    float ez = expf(z - zmax);
    float zsum = block_sum(ez, r8x4 + 16, tid);
    float wc = ez / zsum;

    float wprev = sw_state[tid];
    float wg = gg * wc + (1.f - gg) * wprev;
    s_w[tid] = wg;
    __syncthreads();

    float wt = s_w[(tid + 1) & (NN - 1)] * s0 + wg * s1 + s_w[(tid + NN - 1) & (NN - 1)] * s2;
    float wp = powf(wt + EPSF, gamma);
    float wsum = block_sum(wp, r8x4 + 24, tid);  // internal sync orders s_w reads before writes
    float wn = wp / wsum;
    s_w[tid] = wn;
    sw_state[tid] = wn;
    __syncthreads();
}

// ============================================================================
// Persistent kernel: the whole 256-step recurrence.
//   dyn smem: [0, 32768) memory tile (batch = cta, resident all steps)
//             [32768, 41216) GEMM tile buffers (phases A and B alias this)
// Phases per step (separated by grid barriers):
//   A: h = tanh(r @ Wc[0:128] + xproj[t] + bc)   128 jobs: 16x128 tiles
//   B: pp[z] = h[:,z*256:..] @ Wall[z*256:..]    144 jobs: 18 tiles x splitK 8
//   C: per-batch NTM step (reduce partials, addressing, read, mem update)
// ============================================================================
__global__ void __launch_bounds__(256, 1) ntm_persistent_kernel(
    const float* __restrict__ Wc, const float* __restrict__ bc,
    const float* __restrict__ mem_init, const float* __restrict__ read_init,
    float* __restrict__ out)
{
    extern __shared__ float dyn[];
    float* s_mem = dyn;                 // NN*MM floats
    float* gsm = dyn + NN * MM;         // 8448 floats of GEMM buffers

    const int cta = blockIdx.x;
    const int tid = threadIdx.x;
    const int tx = tid & 15;
    const int ty = tid >> 4;

    __shared__ float s_p[PR + PWD];
    __shared__ float s_w[NN], s_red[NN], s_r8[32], s_e[MM], s_a[MM];
    __shared__ float s_wr[NN], s_ww[NN];

    // per-call state init
    if (cta < BB) {
        const float4* mi = (const float4*)mem_init;
        float4* sm4 = (float4*)s_mem;
        for (int i = tid; i < NN * MM / 4; i += 256) sm4[i] = mi[i];
        for (int i = tid; i < NN; i += 256) { s_wr[i] = 1.f / NN; s_ww[i] = 1.f / NN; }
        if (tid < MM) g_r[cta * MM + tid] = read_init[tid];
    }
    grid_barrier();

    // GEMM smem accessors
    #define AH(buf,k,j) gsm[(buf)*576 + (k)*36 + (j)]
    #define BH(buf,k,j) gsm[1152 + (buf)*2112 + (k)*132 + (j)]
    #define APp(buf,k,j) gsm[(buf)*2112 + (k)*132 + (j)]
    #define BPp(buf,k,j) gsm[4224 + (buf)*2112 + (k)*132 + (j)]

    for (int t = 0; t < TT; t++) {
        // ---------------- phase A: gemm_hr ----------------
        if (cta < 128) {
            const int row0 = (cta >> 4) * 16;
            const int col0 = (cta & 15) * 128;
            const int am = tid >> 4, akk = tid & 15;
            const int bkr = tid >> 5, bn4 = (tid & 31) << 2;

            float avr = g_r[(row0 + am) * MM + akk];
            float4 bvr0 = *(const float4*)(Wc + (size_t)bkr * CC + col0 + bn4);
            float4 bvr1 = *(const float4*)(Wc + (size_t)(bkr + 8) * CC + col0 + bn4);
            *(float2*)&AH(0, akk, 2 * am) = make_float2(avr, avr);
            *(float4*)&BH(0, bkr, bn4) = bvr0;
            *(float4*)&BH(0, bkr + 8, bn4) = bvr1;
            __syncthreads();

            ull acc[4] = {0, 0, 0, 0};
            for (int kt = 0; kt < 8; kt++) {
                int cur = kt & 1;
                if (kt < 7) {
                    int k0 = (kt + 1) * 16;
                    avr = g_r[(row0 + am) * MM + k0 + akk];
                    bvr0 = *(const float4*)(Wc + (size_t)(k0 + bkr) * CC + col0 + bn4);
                    bvr1 = *(const float4*)(Wc + (size_t)(k0 + bkr + 8) * CC + col0 + bn4);
                }
                #pragma unroll
                for (int kk = 0; kk < 16; kk++) {
                    ull a2 = *(const ull*)&AH(cur, kk, ty * 2);
                    ulonglong2 b01 = *(const ulonglong2*)&BH(cur, kk, tx * 8);
                    ulonglong2 b23 = *(const ulonglong2*)&BH(cur, kk, tx * 8 + 4);
                    FFMA2(acc[0], a2, b01.x, acc[0]);
                    FFMA2(acc[1], a2, b01.y, acc[1]);
                    FFMA2(acc[2], a2, b23.x, acc[2]);
                    FFMA2(acc[3], a2, b23.y, acc[3]);
                }
                if (kt < 7) {
                    int nxt = cur ^ 1;
                    *(float2*)&AH(nxt, akk, 2 * am) = make_float2(avr, avr);
                    *(float4*)&BH(nxt, bkr, bn4) = bvr0;
                    *(float4*)&BH(nxt, bkr + 8, bn4) = bvr1;
                    __syncthreads();
                }
            }
            {
                int m = row0 + ty;
                int c = col0 + tx * 8;
                const float* xp = g_xproj + ((size_t)t * BB + m) * CC + c;
                float4 x0 = *(const float4*)(xp);
                float4 x1 = *(const float4*)(xp + 4);
                float4 b0 = *(const float4*)(bc + c);
                float4 b1 = *(const float4*)(bc + c + 4);
                float2 p0 = ull2f2(acc[0]), p1 = ull2f2(acc[1]);
                float2 p2 = ull2f2(acc[2]), p3 = ull2f2(acc[3]);
                float4 v0, v1;
                v0.x = tanhf(p0.x + x0.x + b0.x);
                v0.y = tanhf(p0.y + x0.y + b0.y);
                v0.z = tanhf(p1.x + x0.z + b0.z);
                v0.w = tanhf(p1.y + x0.w + b0.w);
                v1.x = tanhf(p2.x + x1.x + b1.x);
                v1.y = tanhf(p2.y + x1.y + b1.y);
                v1.z = tanhf(p3.x + x1.z + b1.z);
                v1.w = tanhf(p3.y + x1.w + b1.w);
                *(float4*)(g_h + (size_t)m * CC + c)     = v0;
                *(float4*)(g_h + (size_t)m * CC + c + 4) = v1;
            }
        }
        grid_barrier();

        // ---------------- phase B: gemm_p (144 jobs) ----------------
        {
            const int tile = cta % 18;
            const int z = cta / 18;
            const int row0 = (tile / 9) * 64;
            const int col0 = (tile % 9) * 128;
            const int kbase = z * 256;
            const int am = tid >> 2;
            const int akq = (tid & 3) << 2;
            const int bkr = tid >> 5;
            const int bn4 = (tid & 31) << 2;

            float4 avr = *(const float4*)(g_h + (size_t)(row0 + am) * CC + kbase + akq);
            float4 bvr0 = *(const float4*)(g_Wall + (size_t)(kbase + bkr) * PDIMP + col0 + bn4);
            float4 bvr1 = *(const float4*)(g_Wall + (size_t)(kbase + bkr + 8) * PDIMP + col0 + bn4);
            *(float2*)&APp(0, akq + 0, 2 * am) = make_float2(avr.x, avr.x);
            *(float2*)&APp(0, akq + 1, 2 * am) = make_float2(avr.y, avr.y);
            *(float2*)&APp(0, akq + 2, 2 * am) = make_float2(avr.z, avr.z);
            *(float2*)&APp(0, akq + 3, 2 * am) = make_float2(avr.w, avr.w);
            *(float4*)&BPp(0, bkr, bn4) = bvr0;
            *(float4*)&BPp(0, bkr + 8, bn4) = bvr1;
            __syncthreads();

            ull acc[4][4] = {{0,0,0,0},{0,0,0,0},{0,0,0,0},{0,0,0,0}};

            for (int kt = 0; kt < 16; kt++) {
                int cur = kt & 1;
                if (kt < 15) {
                    int k0 = kbase + (kt + 1) * 16;
                    avr = *(const float4*)(g_h + (size_t)(row0 + am) * CC + k0 + akq);
                    bvr0 = *(const float4*)(g_Wall + (size_t)(k0 + bkr) * PDIMP + col0 + bn4);
                    bvr1 = *(const float4*)(g_Wall + (size_t)(k0 + bkr + 8) * PDIMP + col0 + bn4);
                }
                #pragma unroll
                for (int kk = 0; kk < 16; kk++) {
                    ulonglong2 a01 = *(const ulonglong2*)&APp(cur, kk, ty * 8);
                    ulonglong2 a23 = *(const ulonglong2*)&APp(cur, kk, ty * 8 + 4);
                    ulonglong2 b01 = *(const ulonglong2*)&BPp(cur, kk, tx * 8);
                    ulonglong2 b23 = *(const ulonglong2*)&BPp(cur, kk, tx * 8 + 4);
                    ull av[4] = {a01.x, a01.y, a23.x, a23.y};
                    ull bv[4] = {b01.x, b01.y, b23.x, b23.y};
                    #pragma unroll
                    for (int i = 0; i < 4; i++)
                        #pragma unroll
                        for (int j = 0; j < 4; j++)
                            FFMA2(acc[i][j], av[i], bv[j], acc[i][j]);
                }
                if (kt < 15) {
                    int nxt = cur ^ 1;
                    *(float2*)&APp(nxt, akq + 0, 2 * am) = make_float2(avr.x, avr.x);
                    *(float2*)&APp(nxt, akq + 1, 2 * am) = make_float2(avr.y, avr.y);
                    *(float2*)&APp(nxt, akq + 2, 2 * am) = make_float2(avr.z, avr.z);
                    *(float2*)&APp(nxt, akq + 3, 2 * am) = make_float2(avr.w, avr.w);
                    *(float4*)&BPp(nxt, bkr, bn4) = bvr0;
                    *(float4*)&BPp(nxt, bkr + 8, bn4) = bvr1;
                    __syncthreads();
                }
            }

            float* pq = g_pp + (size_t)z * BB * PDIMP;
            #pragma unroll
            for (int i = 0; i < 4; i++) {
                int m = row0 + ty * 4 + i;
                int c = col0 + tx * 8;
                float2 p0 = ull2f2(acc[i][0]), p1 = ull2f2(acc[i][1]);
                float2 p2 = ull2f2(acc[i][2]), p3 = ull2f2(acc[i][3]);
                *(float4*)(pq + (size_t)m * PDIMP + c)     = make_float4(p0.x, p0.y, p1.x, p1.y);
                *(float4*)(pq + (size_t)m * PDIMP + c + 4) = make_float4(p2.x, p2.y, p3.x, p3.y);
            }
        }
        grid_barrier();

        // ---------------- phase C: NTM step ----------------
        if (cta < BB) {
            const int b = cta;

            for (int i = tid; i < PR + PWD; i += 256) {
                float s = g_ball[i];
                #pragma unroll
                for (int ks = 0; ks < SK; ks++)
                    s += g_pp[(size_t)ks * BB * PDIMP + (size_t)b * PDIMP + i];
                s_p[i] = s;
            }
            {
                int c = tid * 2;
                if (c < OUTD) {
                    float v0 = g_ball[PR + PWD + c];
                    float v1 = g_ball[PR + PWD + c + 1];
                    #pragma unroll
                    for (int ks = 0; ks < SK; ks++) {
                        const float* pq = g_pp + (size_t)ks * BB * PDIMP + (size_t)b * PDIMP + PR + PWD + c;
                        v0 += pq[0]; v1 += pq[1];
                    }
                    float* o = out + ((long long)b * TT + t) * OUTD + c;
                    o[0] = v0; o[1] = v1;
                }
            }
            __syncthreads();
            if (tid < MM) {
                s_e[tid] = sigmoidf_(s_p[PR + PR + tid]);
                s_a[tid] = tanhf(s_p[PR + 2 * MM + 6 + tid]);
            }
            __syncthreads();

            // read addressing (old mem)
            address_fn(s_p, s_wr, s_mem, s_w, s_r8, tid);

            // read vector -> g_r
            {
                int m = tid & (MM - 1);
                int half = tid >> 7;
                float acc = 0.f;
                int n0 = half * 128;
                #pragma unroll 8
                for (int n = n0; n < n0 + 128; n++) acc += s_w[n] * s_mem[n * MM + m];
                s_red[tid] = acc;
                __syncthreads();
                if (tid < MM) g_r[b * MM + tid] = s_red[tid] + s_red[tid + 128];
                __syncthreads();
            }

            // write addressing (old mem)
            address_fn(s_p + PR, s_ww, s_mem, s_w, s_r8, tid);

            // memory update in place (smem-resident)
            {
                float4* sm4 = (float4*)s_mem;
                const float4* e4 = (const float4*)s_e;
                const float4* a4 = (const float4*)s_a;
                #pragma unroll 4
                for (int i = tid; i < NN * MM / 4; i += 256) {
                    int n = i >> 5;
                    int m4 = i & 31;
                    float wwn = s_w[n];
                    float4 old = sm4[i];
                    float4 ev = e4[m4];
                    float4 av = a4[m4];
                    float4 r;
                    r.x = old.x * (1.f - wwn * ev.x) + wwn * av.x;
                    r.y = old.y * (1.f - wwn * ev.y) + wwn * av.y;
                    r.z = old.z * (1.f - wwn * ev.z) + wwn * av.z;
                    r.w = old.w * (1.f - wwn * ev.w) + wwn * av.w;
                    sm4[i] = r;
                }
            }
        }
        grid_barrier();
    }
}

// -------- launch --------
extern "C" void kernel_launch(void* const* d_in, const int* in_sizes, int n_in,
                              void* d_out, int out_size) {
    const float* x        = (const float*)d_in[0];
    const float* Wc       = (const float*)d_in[1];
    const float* bc       = (const float*)d_in[2];
    const float* Wout     = (const float*)d_in[3];
    const float* bout     = (const float*)d_in[4];
    const float* Wr       = (const float*)d_in[5];
    const float* br       = (const float*)d_in[6];
    const float* Ww       = (const float*)d_in[7];
    const float* bw       = (const float*)d_in[8];
    const float* mem_init = (const float*)d_in[9];
    const float* read_init= (const float*)d_in[10];
    float* out = (float*)d_out;
    (void)in_sizes; (void)n_in; (void)out_size;

    const int DYNSMEM = (NN * MM + 8448) * (int)sizeof(float);  // 164864 B
    cudaFuncSetAttribute(ntm_persistent_kernel,
                         cudaFuncAttributeMaxDynamicSharedMemorySize, DYNSMEM);

    pack_w_kernel<<<512, 256>>>(Wr, br, Ww, bw, Wout, bout);

    dim3 thr(16, 16);
    dim3 grid_x(CC / 128, (BB * TT) / 64);   // (16, 512)
    xproj_kernel<<<grid_x, thr>>>(x, Wc);

    ntm_persistent_kernel<<<NCTA, 256, DYNSMEM>>>(Wc, bc, mem_init, read_init, out);
}

// round 6
// speedup vs baseline: 2.9834x; 1.3307x over previous
#include <cuda_runtime.h>
#include <math.h>

#define BB 128
#define TT 256
#define INDIM 512
#define CC 2048
#define NN 256
#define MM 128
#define OUTD 512
#define PR 134            // M+6
#define PWD 390           // 3M+6
#define PDIM 1036         // PR + PWD + OUTD
#define PDIMP 1152        // padded to 9*128 col tiles
#define SK 8              // split-K for gemm_p phase (18 tiles * 8 = 144 jobs)
#define NCTA 144
#define EPSF 1e-8f

typedef unsigned long long ull;

// -------- persistent device state --------
__device__ float g_h[BB*CC];
__device__ float g_pp[SK*BB*PDIMP];
__device__ float g_r[BB*MM];
__device__ float g_Wall[CC*PDIMP];
__device__ float g_ball[PDIM];
__device__ float g_xproj[(size_t)TT*BB*CC];  // [t][b][c]
__device__ unsigned g_bar_cnt;
__device__ unsigned g_bar_gen;

#define FFMA2(d, a, b, c) \
    asm("fma.rn.f32x2 %0, %1, %2, %3;" : "=l"(d) : "l"(a), "l"(b), "l"(c))

__device__ __forceinline__ float2 ull2f2(ull v) {
    float2 r;
    r.x = __uint_as_float((unsigned)(v & 0xffffffffULL));
    r.y = __uint_as_float((unsigned)(v >> 32));
    return r;
}

__device__ __forceinline__ float sigmoidf_(float x) { return 1.f / (1.f + expf(-x)); }
__device__ __forceinline__ float softplusf_(float x) {
    return fmaxf(x, 0.f) + log1pf(expf(-fabsf(x)));
}

// -------- software grid barrier (144 CTAs, 1/SM, all resident) --------
__device__ __forceinline__ void grid_barrier() {
    __syncthreads();
    if (threadIdx.x == 0) {
        __threadfence();
        unsigned gen;
        asm volatile("ld.acquire.gpu.u32 %0, [%1];" : "=r"(gen) : "l"(&g_bar_gen) : "memory");
        if (atomicAdd(&g_bar_cnt, 1u) == NCTA - 1) {
            atomicExch(&g_bar_cnt, 0u);
            __threadfence();
            atomicExch(&g_bar_gen, gen + 1u);
        } else {
            unsigned cur;
            do {
                asm volatile("ld.acquire.gpu.u32 %0, [%1];" : "=r"(cur) : "l"(&g_bar_gen) : "memory");
            } while (cur == gen);
        }
    }
    __syncthreads();
}

// -------- init: pack projection weights --------
__global__ void pack_w_kernel(const float* __restrict__ Wr, const float* __restrict__ br,
                              const float* __restrict__ Ww, const float* __restrict__ bw,
                              const float* __restrict__ Wout, const float* __restrict__ bout) {
    int gid = blockIdx.x * blockDim.x + threadIdx.x;
    int stride = gridDim.x * blockDim.x;
    for (int i = gid; i < PDIM; i += stride) {
        float v;
        if (i < PR) v = br[i];
        else if (i < PR + PWD) v = bw[i - PR];
        else v = bout[i - PR - PWD];
        g_ball[i] = v;
    }
    int total = CC * PDIMP;
    for (int idx = gid; idx < total; idx += stride) {
        int row = idx / PDIMP, col = idx % PDIMP;
        float v = 0.f;
        if (col < PR) v = Wr[row * PR + col];
        else if (col < PR + PWD) v = Ww[row * PWD + (col - PR)];
        else if (col < PDIM) v = Wout[row * OUTD + (col - PR - PWD)];
        g_Wall[idx] = v;
    }
}

// -------- xproj = x[B*T, 512] @ Wc[128:640, :]  -> stored [t][b][c] --------
// BM=64, BN=128, BK=16; micro 4 rows x (4 + 4 cols, 16B-strided chunks)
__global__ void __launch_bounds__(256, 2) xproj_kernel(const float* __restrict__ x,
                                                       const float* __restrict__ Wc) {
    __shared__ __align__(16) float As2[2][16][132];
    __shared__ __align__(16) float Bs[2][16][132];
    const int tx = threadIdx.x, ty = threadIdx.y;
    const int tid = ty * 16 + tx;
    const long long row0 = (long long)blockIdx.y * 64;
    const int col0 = blockIdx.x * 128;

    const int am = tid >> 2;
    const int akq = (tid & 3) << 2;
    const int bkr = tid >> 5;
    const int bn4 = (tid & 31) << 2;

    const int KT = INDIM / 16;  // 32
    float4 avr, bvr0, bvr1;

    {
        avr = *(const float4*)(x + (row0 + am) * INDIM + akq);
        bvr0 = *(const float4*)(Wc + (size_t)(MM + bkr) * CC + col0 + bn4);
        bvr1 = *(const float4*)(Wc + (size_t)(MM + bkr + 8) * CC + col0 + bn4);
        *(float2*)&As2[0][akq + 0][2 * am] = make_float2(avr.x, avr.x);
        *(float2*)&As2[0][akq + 1][2 * am] = make_float2(avr.y, avr.y);
        *(float2*)&As2[0][akq + 2][2 * am] = make_float2(avr.z, avr.z);
        *(float2*)&As2[0][akq + 3][2 * am] = make_float2(avr.w, avr.w);
        *(float4*)&Bs[0][bkr][bn4] = bvr0;
        *(float4*)&Bs[0][bkr + 8][bn4] = bvr1;
    }
    __syncthreads();

    ull acc[4][4] = {{0,0,0,0},{0,0,0,0},{0,0,0,0},{0,0,0,0}};

    for (int kt = 0; kt < KT; kt++) {
        int cur = kt & 1;
        if (kt + 1 < KT) {
            int k0 = (kt + 1) * 16;
            avr = *(const float4*)(x + (row0 + am) * INDIM + k0 + akq);
            bvr0 = *(const float4*)(Wc + (size_t)(MM + k0 + bkr) * CC + col0 + bn4);
            bvr1 = *(const float4*)(Wc + (size_t)(MM + k0 + bkr + 8) * CC + col0 + bn4);
        }
        #pragma unroll
        for (int kk = 0; kk < 16; kk++) {
            ulonglong2 a01 = *(const ulonglong2*)&As2[cur][kk][ty * 8];
            ulonglong2 a23 = *(const ulonglong2*)&As2[cur][kk][ty * 8 + 4];
            // two 16B-strided column chunks: cols [tx*4, +4) and [64+tx*4, +4)
            ulonglong2 b01 = *(const ulonglong2*)&Bs[cur][kk][tx * 4];
            ulonglong2 b23 = *(const ulonglong2*)&Bs[cur][kk][64 + tx * 4];
            ull av[4] = {a01.x, a01.y, a23.x, a23.y};
            ull bv[4] = {b01.x, b01.y, b23.x, b23.y};
            #pragma unroll
            for (int i = 0; i < 4; i++)
                #pragma unroll
                for (int j = 0; j < 4; j++)
                    FFMA2(acc[i][j], av[i], bv[j], acc[i][j]);
        }
        if (kt + 1 < KT) {
            int nxt = cur ^ 1;
            *(float2*)&As2[nxt][akq + 0][2 * am] = make_float2(avr.x, avr.x);
            *(float2*)&As2[nxt][akq + 1][2 * am] = make_float2(avr.y, avr.y);
            *(float2*)&As2[nxt][akq + 2][2 * am] = make_float2(avr.z, avr.z);
            *(float2*)&As2[nxt][akq + 3][2 * am] = make_float2(avr.w, avr.w);
            *(float4*)&Bs[nxt][bkr][bn4] = bvr0;
            *(float4*)&Bs[nxt][bkr + 8][bn4] = bvr1;
            __syncthreads();
        }
    }

    #pragma unroll
    for (int i = 0; i < 4; i++) {
        long long rid = row0 + ty * 4 + i;     // rid = b*TT + t
        int bb = (int)(rid >> 8);
        int tt = (int)(rid & 255);
        float* dst = g_xproj + ((size_t)tt * BB + bb) * CC + col0;
        float2 p0 = ull2f2(acc[i][0]), p1 = ull2f2(acc[i][1]);
        float2 p2 = ull2f2(acc[i][2]), p3 = ull2f2(acc[i][3]);
        *(float4*)(dst + tx * 4)      = make_float4(p0.x, p0.y, p1.x, p1.y);
        *(float4*)(dst + 64 + tx * 4) = make_float4(p2.x, p2.y, p3.x, p3.y);
    }
}

// -------- block reductions --------
__device__ __forceinline__ float warp_red_sum(float v) {
    #pragma unroll
    for (int o = 16; o; o >>= 1) v += __shfl_xor_sync(0xffffffffu, v, o);
    return v;
}
__device__ __forceinline__ float warp_red_max(float v) {
    #pragma unroll
    for (int o = 16; o; o >>= 1) v = fmaxf(v, __shfl_xor_sync(0xffffffffu, v, o));
    return v;
}
__device__ __forceinline__ float block_sum(float v, float* r8, int tid) {
    v = warp_red_sum(v);
    if ((tid & 31) == 0) r8[tid >> 5] = v;
    __syncthreads();
    float s = 0.f;
    #pragma unroll
    for (int i = 0; i < 8; i++) s += r8[i];
    return s;
}
__device__ __forceinline__ float block_max(float v, float* r8, int tid) {
    v = warp_red_max(v);
    if ((tid & 31) == 0) r8[tid >> 5] = v;
    __syncthreads();
    float s = r8[0];
    #pragma unroll
    for (int i = 1; i < 8; i++) s = fmaxf(s, r8[i]);
    return s;
}

__device__ void address_fn(const float* __restrict__ pp, float* __restrict__ sw_state,
                           const float* __restrict__ s_mem,
                           float* __restrict__ s_w, float* __restrict__ r8x4, int tid) {
    float kv = (tid < MM) ? pp[tid] : 0.f;
    float knorm = sqrtf(block_sum(kv * kv, r8x4 + 0, tid));
    float beta  = softplusf_(pp[MM]);
    float gg    = sigmoidf_(pp[MM + 1]);
    float p2 = pp[MM + 2], p3 = pp[MM + 3], p4 = pp[MM + 4];
    float smax = fmaxf(p2, fmaxf(p3, p4));
    float e0 = expf(p2 - smax), e1 = expf(p3 - smax), e2 = expf(p4 - smax);
    float einv = 1.f / (e0 + e1 + e2);
    float s0 = e0 * einv, s1 = e1 * einv, s2 = e2 * einv;
    float gamma = 1.f + softplusf_(pp[MM + 5]);

    // cosine similarity, row n = tid; 4 independent accumulator chains
    float d0 = 0.f, d1 = 0.f, d2 = 0.f, d3 = 0.f;
    float q0 = 0.f, q1 = 0.f, q2 = 0.f, q3 = 0.f;
    const int base = tid * MM;
    #pragma unroll 4
    for (int j = 0; j < MM; j += 4) {
        int m0 = (j + 0 + tid) & (MM - 1);
        int m1 = (j + 1 + tid) & (MM - 1);
        int m2 = (j + 2 + tid) & (MM - 1);
        int m3 = (j + 3 + tid) & (MM - 1);
        float v0 = s_mem[base + m0], v1 = s_mem[base + m1];
        float v2 = s_mem[base + m2], v3 = s_mem[base + m3];
        d0 += pp[m0] * v0; q0 += v0 * v0;
        d1 += pp[m1] * v1; q1 += v1 * v1;
        d2 += pp[m2] * v2; q2 += v2 * v2;
        d3 += pp[m3] * v3; q3 += v3 * v3;
    }
    float dot = (d0 + d1) + (d2 + d3);
    float msq = (q0 + q1) + (q2 + q3);
    float sim = dot / (knorm * sqrtf(msq) + EPSF);

    float z = beta * sim;
    float zmax = block_max(z, r8x4 + 8, tid);
    float ez = expf(z - zmax);
    float zsum = block_sum(ez, r8x4 + 16, tid);
    float wc = ez / zsum;

    float wprev = sw_state[tid];
    float wg = gg * wc + (1.f - gg) * wprev;
    s_w[tid] = wg;
    __syncthreads();

    float wt = s_w[(tid + 1) & (NN - 1)] * s0 + wg * s1 + s_w[(tid + NN - 1) & (NN - 1)] * s2;
    float wp = powf(wt + EPSF, gamma);
    float wsum = block_sum(wp, r8x4 + 24, tid);
    float wn = wp / wsum;
    s_w[tid] = wn;
    sw_state[tid] = wn;
    __syncthreads();
}

// ============================================================================
// Persistent kernel: whole 256-step recurrence.
// ============================================================================
__global__ void __launch_bounds__(256, 1) ntm_persistent_kernel(
    const float* __restrict__ Wc, const float* __restrict__ bc,
    const float* __restrict__ mem_init, const float* __restrict__ read_init,
    float* __restrict__ out)
{
    extern __shared__ float dyn[];
    float* s_mem = dyn;                 // NN*MM floats
    float* gsm = dyn + NN * MM;         // GEMM tile buffers

    const int cta = blockIdx.x;
    const int tid = threadIdx.x;
    const int tx = tid & 15;
    const int ty = tid >> 4;

    __shared__ float s_p[PR + PWD];
    __shared__ float s_w[NN], s_red[NN], s_r8[32], s_e[MM], s_a[MM];
    __shared__ float s_wr[NN], s_ww[NN];

    if (cta < BB) {
        const float4* mi = (const float4*)mem_init;
        float4* sm4 = (float4*)s_mem;
        for (int i = tid; i < NN * MM / 4; i += 256) sm4[i] = mi[i];
        for (int i = tid; i < NN; i += 256) { s_wr[i] = 1.f / NN; s_ww[i] = 1.f / NN; }
        if (tid < MM) g_r[cta * MM + tid] = read_init[tid];
    }
    grid_barrier();

    #define AH(buf,k,j) gsm[(buf)*576 + (k)*36 + (j)]
    #define BH(buf,k,j) gsm[1152 + (buf)*2112 + (k)*132 + (j)]
    #define APp(buf,k,j) gsm[(buf)*2112 + (k)*132 + (j)]
    #define BPp(buf,k,j) gsm[4224 + (buf)*2112 + (k)*132 + (j)]

    for (int t = 0; t < TT; t++) {
        // ---------------- phase A: h = tanh(r @ Wc[0:128] + xproj + bc) ----------------
        if (cta < 128) {
            const int row0 = (cta >> 4) * 16;
            const int col0 = (cta & 15) * 128;
            const int am = tid >> 4, akk = tid & 15;
            const int bkr = tid >> 5, bn4 = (tid & 31) << 2;

            float avr = g_r[(row0 + am) * MM + akk];
            float4 bvr0 = *(const float4*)(Wc + (size_t)bkr * CC + col0 + bn4);
            float4 bvr1 = *(const float4*)(Wc + (size_t)(bkr + 8) * CC + col0 + bn4);
            *(float2*)&AH(0, akk, 2 * am) = make_float2(avr, avr);
            *(float4*)&BH(0, bkr, bn4) = bvr0;
            *(float4*)&BH(0, bkr + 8, bn4) = bvr1;
            __syncthreads();

            ull acc[4] = {0, 0, 0, 0};
            for (int kt = 0; kt < 8; kt++) {
                int cur = kt & 1;
                if (kt < 7) {
                    int k0 = (kt + 1) * 16;
                    avr = g_r[(row0 + am) * MM + k0 + akk];
                    bvr0 = *(const float4*)(Wc + (size_t)(k0 + bkr) * CC + col0 + bn4);
                    bvr1 = *(const float4*)(Wc + (size_t)(k0 + bkr + 8) * CC + col0 + bn4);
                }
                #pragma unroll
                for (int kk = 0; kk < 16; kk++) {
                    ull a2 = *(const ull*)&AH(cur, kk, ty * 2);
                    ulonglong2 b01 = *(const ulonglong2*)&BH(cur, kk, tx * 4);
                    ulonglong2 b23 = *(const ulonglong2*)&BH(cur, kk, 64 + tx * 4);
                    FFMA2(acc[0], a2, b01.x, acc[0]);
                    FFMA2(acc[1], a2, b01.y, acc[1]);
                    FFMA2(acc[2], a2, b23.x, acc[2]);
                    FFMA2(acc[3], a2, b23.y, acc[3]);
                }
                if (kt < 7) {
                    int nxt = cur ^ 1;
                    *(float2*)&AH(nxt, akk, 2 * am) = make_float2(avr, avr);
                    *(float4*)&BH(nxt, bkr, bn4) = bvr0;
                    *(float4*)&BH(nxt, bkr + 8, bn4) = bvr1;
                    __syncthreads();
                }
            }
            {
                int m = row0 + ty;
                const float* xp = g_xproj + ((size_t)t * BB + m) * CC + col0;
                float4 x0 = *(const float4*)(xp + tx * 4);
                float4 x1 = *(const float4*)(xp + 64 + tx * 4);
                float4 b0 = *(const float4*)(bc + col0 + tx * 4);
                float4 b1 = *(const float4*)(bc + col0 + 64 + tx * 4);
                float2 p0 = ull2f2(acc[0]), p1 = ull2f2(acc[1]);
                float2 p2 = ull2f2(acc[2]), p3 = ull2f2(acc[3]);
                float4 v0, v1;
                v0.x = tanhf(p0.x + x0.x + b0.x);
                v0.y = tanhf(p0.y + x0.y + b0.y);
                v0.z = tanhf(p1.x + x0.z + b0.z);
                v0.w = tanhf(p1.y + x0.w + b0.w);
                v1.x = tanhf(p2.x + x1.x + b1.x);
                v1.y = tanhf(p2.y + x1.y + b1.y);
                v1.z = tanhf(p3.x + x1.z + b1.z);
                v1.w = tanhf(p3.y + x1.w + b1.w);
                *(float4*)(g_h + (size_t)m * CC + col0 + tx * 4)      = v0;
                *(float4*)(g_h + (size_t)m * CC + col0 + 64 + tx * 4) = v1;
            }
        }
        grid_barrier();

        // ---------------- phase B: gemm_p (144 jobs: 18 tiles x splitK 8) ----------------
        {
            const int tile = cta % 18;
            const int z = cta / 18;
            const int row0 = (tile / 9) * 64;
            const int col0 = (tile % 9) * 128;
            const int kbase = z * 256;
            const int am = tid >> 2;
            const int akq = (tid & 3) << 2;
            const int bkr = tid >> 5;
            const int bn4 = (tid & 31) << 2;

            float4 avr = *(const float4*)(g_h + (size_t)(row0 + am) * CC + kbase + akq);
            float4 bvr0 = *(const float4*)(g_Wall + (size_t)(kbase + bkr) * PDIMP + col0 + bn4);
            float4 bvr1 = *(const float4*)(g_Wall + (size_t)(kbase + bkr + 8) * PDIMP + col0 + bn4);
            *(float2*)&APp(0, akq + 0, 2 * am) = make_float2(avr.x, avr.x);
            *(float2*)&APp(0, akq + 1, 2 * am) = make_float2(avr.y, avr.y);
            *(float2*)&APp(0, akq + 2, 2 * am) = make_float2(avr.z, avr.z);
            *(float2*)&APp(0, akq + 3, 2 * am) = make_float2(avr.w, avr.w);
            *(float4*)&BPp(0, bkr, bn4) = bvr0;
            *(float4*)&BPp(0, bkr + 8, bn4) = bvr1;
            __syncthreads();

            ull acc[4][4] = {{0,0,0,0},{0,0,0,0},{0,0,0,0},{0,0,0,0}};

            for (int kt = 0; kt < 16; kt++) {
                int cur = kt & 1;
                if (kt < 15) {
                    int k0 = kbase + (kt + 1) * 16;
                    avr = *(const float4*)(g_h + (size_t)(row0 + am) * CC + k0 + akq);
                    bvr0 = *(const float4*)(g_Wall + (size_t)(k0 + bkr) * PDIMP + col0 + bn4);
                    bvr1 = *(const float4*)(g_Wall + (size_t)(k0 + bkr + 8) * PDIMP + col0 + bn4);
                }
                #pragma unroll
                for (int kk = 0; kk < 16; kk++) {
                    ulonglong2 a01 = *(const ulonglong2*)&APp(cur, kk, ty * 8);
                    ulonglong2 a23 = *(const ulonglong2*)&APp(cur, kk, ty * 8 + 4);
                    ulonglong2 b01 = *(const ulonglong2*)&BPp(cur, kk, tx * 4);
                    ulonglong2 b23 = *(const ulonglong2*)&BPp(cur, kk, 64 + tx * 4);
                    ull av[4] = {a01.x, a01.y, a23.x, a23.y};
                    ull bv[4] = {b01.x, b01.y, b23.x, b23.y};
                    #pragma unroll
                    for (int i = 0; i < 4; i++)
                        #pragma unroll
                        for (int j = 0; j < 4; j++)
                            FFMA2(acc[i][j], av[i], bv[j], acc[i][j]);
                }
                if (kt < 15) {
                    int nxt = cur ^ 1;
                    *(float2*)&APp(nxt, akq + 0, 2 * am) = make_float2(avr.x, avr.x);
                    *(float2*)&APp(nxt, akq + 1, 2 * am) = make_float2(avr.y, avr.y);
                    *(float2*)&APp(nxt, akq + 2, 2 * am) = make_float2(avr.z, avr.z);
                    *(float2*)&APp(nxt, akq + 3, 2 * am) = make_float2(avr.w, avr.w);
                    *(float4*)&BPp(nxt, bkr, bn4) = bvr0;
                    *(float4*)&BPp(nxt, bkr + 8, bn4) = bvr1;
                    __syncthreads();
                }
            }

            float* pq = g_pp + (size_t)z * BB * PDIMP;
            #pragma unroll
            for (int i = 0; i < 4; i++) {
                int m = row0 + ty * 4 + i;
                float2 p0 = ull2f2(acc[i][0]), p1 = ull2f2(acc[i][1]);
                float2 p2 = ull2f2(acc[i][2]), p3 = ull2f2(acc[i][3]);
                *(float4*)(pq + (size_t)m * PDIMP + col0 + tx * 4)      = make_float4(p0.x, p0.y, p1.x, p1.y);
                *(float4*)(pq + (size_t)m * PDIMP + col0 + 64 + tx * 4) = make_float4(p2.x, p2.y, p3.x, p3.y);
            }
        }
        grid_barrier();

        // ---------------- phase C: NTM step ----------------
        if (cta < BB) {
            const int b = cta;

            for (int i = tid; i < PR + PWD; i += 256) {
                float s = g_ball[i];
                #pragma unroll
                for (int ks = 0; ks < SK; ks++)
                    s += g_pp[(size_t)ks * BB * PDIMP + (size_t)b * PDIMP + i];
                s_p[i] = s;
            }
            {
                int c = tid * 2;
                if (c < OUTD) {
                    float v0 = g_ball[PR + PWD + c];
                    float v1 = g_ball[PR + PWD + c + 1];
                    #pragma unroll
                    for (int ks = 0; ks < SK; ks++) {
                        const float* pq = g_pp + (size_t)ks * BB * PDIMP + (size_t)b * PDIMP + PR + PWD + c;
                        v0 += pq[0]; v1 += pq[1];
                    }
                    float* o = out + ((long long)b * TT + t) * OUTD + c;
                    o[0] = v0; o[1] = v1;
                }
            }
            __syncthreads();
            if (tid < MM) {
                s_e[tid] = sigmoidf_(s_p[PR + PR + tid]);
                s_a[tid] = tanhf(s_p[PR + 2 * MM + 6 + tid]);
            }
            __syncthreads();

            address_fn(s_p, s_wr, s_mem, s_w, s_r8, tid);

            // read vector -> g_r (4 accumulator chains)
            {
                int m = tid & (MM - 1);
                int half = tid >> 7;
                int n0 = half * 128;
                float a0 = 0.f, a1 = 0.f, a2 = 0.f, a3 = 0.f;
                #pragma unroll 4
                for (int n = n0; n < n0 + 128; n += 4) {
                    a0 += s_w[n + 0] * s_mem[(n + 0) * MM + m];
                    a1 += s_w[n + 1] * s_mem[(n + 1) * MM + m];
                    a2 += s_w[n + 2] * s_mem[(n + 2) * MM + m];
                    a3 += s_w[n + 3] * s_mem[(n + 3) * MM + m];
                }
                s_red[tid] = (a0 + a1) + (a2 + a3);
                __syncthreads();
                if (tid < MM) g_r[b * MM + tid] = s_red[tid] + s_red[tid + 128];
                __syncthreads();
            }

            address_fn(s_p + PR, s_ww, s_mem, s_w, s_r8, tid);

            // memory update in place
            {
                float4* sm4 = (float4*)s_mem;
                const float4* e4 = (const float4*)s_e;
                const float4* a4 = (const float4*)s_a;
                #pragma unroll 4
                for (int i = tid; i < NN * MM / 4; i += 256) {
                    int n = i >> 5;
                    int m4 = i & 31;
                    float wwn = s_w[n];
                    float4 old = sm4[i];
                    float4 ev = e4[m4];
                    float4 av = a4[m4];
                    float4 r;
                    r.x = old.x * (1.f - wwn * ev.x) + wwn * av.x;
                    r.y = old.y * (1.f - wwn * ev.y) + wwn * av.y;
                    r.z = old.z * (1.f - wwn * ev.z) + wwn * av.z;
                    r.w = old.w * (1.f - wwn * ev.w) + wwn * av.w;
                    sm4[i] = r;
                }
            }
        }
        grid_barrier();
    }
}

// -------- launch --------
extern "C" void kernel_launch(void* const* d_in, const int* in_sizes, int n_in,
                              void* d_out, int out_size) {
    const float* x        = (const float*)d_in[0];
    const float* Wc       = (const float*)d_in[1];
    const float* bc       = (const float*)d_in[2];
    const float* Wout     = (const float*)d_in[3];
    const float* bout     = (const float*)d_in[4];
    const float* Wr       = (const float*)d_in[5];
    const float* br       = (const float*)d_in[6];
    const float* Ww       = (const float*)d_in[7];
    const float* bw       = (const float*)d_in[8];
    const float* mem_init = (const float*)d_in[9];
    const float* read_init= (const float*)d_in[10];
    float* out = (float*)d_out;
    (void)in_sizes; (void)n_in; (void)out_size;

    const int DYNSMEM = (NN * MM + 8448) * (int)sizeof(float);  // 164864 B
    cudaFuncSetAttribute(ntm_persistent_kernel,
                         cudaFuncAttributeMaxDynamicSharedMemorySize, DYNSMEM);

    pack_w_kernel<<<512, 256>>>(Wr, br, Ww, bw, Wout, bout);

    dim3 thr(16, 16);
    dim3 grid_x(CC / 128, (BB * TT) / 64);   // (16, 512)
    xproj_kernel<<<grid_x, thr>>>(x, Wc);

    ntm_persistent_kernel<<<NCTA, 256, DYNSMEM>>>(Wc, bc, mem_init, read_init, out);
}

// round 9
// speedup vs baseline: 3.6323x; 1.2175x over previous
#include <cuda_runtime.h>
#include <cuda_bf16.h>
#include <math.h>
#include <stdint.h>

#define BB 128
#define TT 256
#define INDIM 512
#define CC 2048
#define NN 256
#define MM 128
#define OUTD 512
#define PR 134            // M+6
#define PWD 390           // 3M+6
#define PDIM 1036         // PR + PWD + OUTD
#define PDIMP 1152        // 9*128 col tiles
#define SK 16             // split-K for phase B (9 coltiles * 16 = 144 jobs)
#define NCTA 144
#define EPSF 1e-8f

typedef unsigned long long ull;

// -------- persistent device state --------
__device__ float g_pp[SK*BB*PDIMP];                       // split-K partials
__device__ float g_r[BB*MM];
__device__ __align__(16) __nv_bfloat16 g_hhi[BB*CC];      // h split hi/lo (row-major)
__device__ __align__(16) __nv_bfloat16 g_hlo[BB*CC];
__device__ __align__(16) __nv_bfloat16 g_wthi[PDIMP*CC];  // Wall^T split hi/lo: [n][k]
__device__ __align__(16) __nv_bfloat16 g_wtlo[PDIMP*CC];
__device__ float g_ball[PDIM];
__device__ float g_xproj[(size_t)TT*BB*CC];               // [t][b][c]
__device__ unsigned g_bar_cnt;
__device__ unsigned g_bar_gen;

// -------- f32x2 FMA --------
#define FFMA2(d, a, b, c) \
    asm("fma.rn.f32x2 %0, %1, %2, %3;" : "=l"(d) : "l"(a), "l"(b), "l"(c))

__device__ __forceinline__ float2 ull2f2(ull v) {
    float2 r;
    r.x = __uint_as_float((unsigned)(v & 0xffffffffULL));
    r.y = __uint_as_float((unsigned)(v >> 32));
    return r;
}

__device__ __forceinline__ float sigmoidf_(float x) { return 1.f / (1.f + expf(-x)); }
__device__ __forceinline__ float softplusf_(float x) {
    return fmaxf(x, 0.f) + log1pf(expf(-fabsf(x)));
}

// -------- mma.sync / ldmatrix helpers (plain sm_103, no 'a' features) --------
__device__ __forceinline__ uint32_t s2u(const void* p) {
    uint32_t a;
    asm("{ .reg .u64 t; cvta.to.shared.u64 t, %1; cvt.u32.u64 %0, t; }" : "=r"(a) : "l"(p));
    return a;
}
__device__ __forceinline__ uint32_t swz128(uint32_t o) { return o ^ ((o >> 3) & 0x70); }

#define LDSM_X4(r, addr) \
    asm volatile("ldmatrix.sync.aligned.m8n8.x4.shared.b16 {%0,%1,%2,%3}, [%4];" \
        : "=r"((r)[0]), "=r"((r)[1]), "=r"((r)[2]), "=r"((r)[3]) : "r"(addr))

#define MMA_BF16(d, a, b0_, b1_) \
    asm volatile("mma.sync.aligned.m16n8k16.row.col.f32.bf16.bf16.f32 " \
        "{%0,%1,%2,%3}, {%4,%5,%6,%7}, {%8,%9}, {%0,%1,%2,%3};" \
        : "+f"((d)[0]), "+f"((d)[1]), "+f"((d)[2]), "+f"((d)[3]) \
        : "r"((a)[0]), "r"((a)[1]), "r"((a)[2]), "r"((a)[3]), "r"(b0_), "r"(b1_))

// -------- software grid barrier (144 CTAs, 1/SM, all resident) --------
__device__ __forceinline__ void grid_barrier() {
    __syncthreads();
    if (threadIdx.x == 0) {
        __threadfence();
        unsigned gen;
        asm volatile("ld.acquire.gpu.u32 %0, [%1];" : "=r"(gen) : "l"(&g_bar_gen) : "memory");
        if (atomicAdd(&g_bar_cnt, 1u) == NCTA - 1) {
            atomicExch(&g_bar_cnt, 0u);
            __threadfence();
            atomicExch(&g_bar_gen, gen + 1u);
        } else {
            unsigned cur;
            do {
                asm volatile("ld.acquire.gpu.u32 %0, [%1];" : "=r"(cur) : "l"(&g_bar_gen) : "memory");
            } while (cur == gen);
        }
    }
    __syncthreads();
}

// -------- init: pack transposed bf16 hi/lo weights + bias --------
__global__ void pack_w_kernel(const float* __restrict__ Wr, const float* __restrict__ br,
                              const float* __restrict__ Ww, const float* __restrict__ bw,
                              const float* __restrict__ Wout, const float* __restrict__ bout) {
    int gid = blockIdx.x * blockDim.x + threadIdx.x;
    int stride = gridDim.x * blockDim.x;
    for (int i = gid; i < PDIM; i += stride) {
        float v;
        if (i < PR) v = br[i];
        else if (i < PR + PWD) v = bw[i - PR];
        else v = bout[i - PR - PWD];
        g_ball[i] = v;
    }
    int total = PDIMP * CC;
    for (int idx = gid; idx < total; idx += stride) {
        int n = idx / CC, k = idx % CC;
        float v = 0.f;
        if (n < PR) v = Wr[k * PR + n];
        else if (n < PR + PWD) v = Ww[k * PWD + (n - PR)];
        else if (n < PDIM) v = Wout[k * OUTD + (n - PR - PWD)];
        __nv_bfloat16 hi = __float2bfloat16_rn(v);
        g_wthi[idx] = hi;
        g_wtlo[idx] = __float2bfloat16_rn(v - __bfloat162float(hi));
    }
}

// -------- xproj = x[B*T, 512] @ Wc[128:640, :]  -> [t][b][c] --------
__global__ void __launch_bounds__(256, 2) xproj_kernel(const float* __restrict__ x,
                                                       const float* __restrict__ Wc) {
    __shared__ __align__(16) float As2[2][16][132];
    __shared__ __align__(16) float Bs[2][16][132];
    const int tx = threadIdx.x, ty = threadIdx.y;
    const int tid = ty * 16 + tx;
    const long long row0 = (long long)blockIdx.y * 64;
    const int col0 = blockIdx.x * 128;

    const int am = tid >> 2;
    const int akq = (tid & 3) << 2;
    const int bkr = tid >> 5;
    const int bn4 = (tid & 31) << 2;

    const int KT = INDIM / 16;
    float4 avr, bvr0, bvr1;

    {
        avr = *(const float4*)(x + (row0 + am) * INDIM + akq);
        bvr0 = *(const float4*)(Wc + (size_t)(MM + bkr) * CC + col0 + bn4);
        bvr1 = *(const float4*)(Wc + (size_t)(MM + bkr + 8) * CC + col0 + bn4);
        *(float2*)&As2[0][akq + 0][2 * am] = make_float2(avr.x, avr.x);
        *(float2*)&As2[0][akq + 1][2 * am] = make_float2(avr.y, avr.y);
        *(float2*)&As2[0][akq + 2][2 * am] = make_float2(avr.z, avr.z);
        *(float2*)&As2[0][akq + 3][2 * am] = make_float2(avr.w, avr.w);
        *(float4*)&Bs[0][bkr][bn4] = bvr0;
        *(float4*)&Bs[0][bkr + 8][bn4] = bvr1;
    }
    __syncthreads();

    ull acc[4][4] = {{0,0,0,0},{0,0,0,0},{0,0,0,0},{0,0,0,0}};

    for (int kt = 0; kt < KT; kt++) {
        int cur = kt & 1;
        if (kt + 1 < KT) {
            int k0 = (kt + 1) * 16;
            avr = *(const float4*)(x + (row0 + am) * INDIM + k0 + akq);
            bvr0 = *(const float4*)(Wc + (size_t)(MM + k0 + bkr) * CC + col0 + bn4);
            bvr1 = *(const float4*)(Wc + (size_t)(MM + k0 + bkr + 8) * CC + col0 + bn4);
        }
        #pragma unroll
        for (int kk = 0; kk < 16; kk++) {
            ulonglong2 a01 = *(const ulonglong2*)&As2[cur][kk][ty * 8];
            ulonglong2 a23 = *(const ulonglong2*)&As2[cur][kk][ty * 8 + 4];
            ulonglong2 b01 = *(const ulonglong2*)&Bs[cur][kk][tx * 4];
            ulonglong2 b23 = *(const ulonglong2*)&Bs[cur][kk][64 + tx * 4];
            ull av[4] = {a01.x, a01.y, a23.x, a23.y};
            ull bv[4] = {b01.x, b01.y, b23.x, b23.y};
            #pragma unroll
            for (int i = 0; i < 4; i++)
                #pragma unroll
                for (int j = 0; j < 4; j++)
                    FFMA2(acc[i][j], av[i], bv[j], acc[i][j]);
        }
        if (kt + 1 < KT) {
            int nxt = cur ^ 1;
            *(float2*)&As2[nxt][akq + 0][2 * am] = make_float2(avr.x, avr.x);
            *(float2*)&As2[nxt][akq + 1][2 * am] = make_float2(avr.y, avr.y);
            *(float2*)&As2[nxt][akq + 2][2 * am] = make_float2(avr.z, avr.z);
            *(float2*)&As2[nxt][akq + 3][2 * am] = make_float2(avr.w, avr.w);
            *(float4*)&Bs[nxt][bkr][bn4] = bvr0;
            *(float4*)&Bs[nxt][bkr + 8][bn4] = bvr1;
            __syncthreads();
        }
    }

    #pragma unroll
    for (int i = 0; i < 4; i++) {
        long long rid = row0 + ty * 4 + i;
        int bb = (int)(rid >> 8);
        int tt = (int)(rid & 255);
        float* dst = g_xproj + ((size_t)tt * BB + bb) * CC + col0;
        float2 p0 = ull2f2(acc[i][0]), p1 = ull2f2(acc[i][1]);
        float2 p2 = ull2f2(acc[i][2]), p3 = ull2f2(acc[i][3]);
        *(float4*)(dst + tx * 4)      = make_float4(p0.x, p0.y, p1.x, p1.y);
        *(float4*)(dst + 64 + tx * 4) = make_float4(p2.x, p2.y, p3.x, p3.y);
    }
}

// -------- block reductions --------
__device__ __forceinline__ float warp_red_sum(float v) {
    #pragma unroll
    for (int o = 16; o; o >>= 1) v += __shfl_xor_sync(0xffffffffu, v, o);
    return v;
}
__device__ __forceinline__ float warp_red_max(float v) {
    #pragma unroll
    for (int o = 16; o; o >>= 1) v = fmaxf(v, __shfl_xor_sync(0xffffffffu, v, o));
    return v;
}
__device__ __forceinline__ float block_sum(float v, float* r8, int tid) {
    v = warp_red_sum(v);
    if ((tid & 31) == 0) r8[tid >> 5] = v;
    __syncthreads();
    float s = 0.f;
    #pragma unroll
    for (int i = 0; i < 8; i++) s += r8[i];
    return s;
}
__device__ __forceinline__ float block_max(float v, float* r8, int tid) {
    v = warp_red_max(v);
    if ((tid & 31) == 0) r8[tid >> 5] = v;
    __syncthreads();
    float s = r8[0];
    #pragma unroll
    for (int i = 1; i < 8; i++) s = fmaxf(s, r8[i]);
    return s;
}

__device__ void address_fn(const float* __restrict__ pp, float* __restrict__ sw_state,
                           const float* __restrict__ s_mem,
                           float* __restrict__ s_w, float* __restrict__ r8x4, int tid) {
    float kv = (tid < MM) ? pp[tid] : 0.f;
    float knorm = sqrtf(block_sum(kv * kv, r8x4 + 0, tid));
    float beta  = softplusf_(pp[MM]);
    float gg    = sigmoidf_(pp[MM + 1]);
    float p2 = pp[MM + 2], p3 = pp[MM + 3], p4 = pp[MM + 4];
    float smax = fmaxf(p2, fmaxf(p3, p4));
    float e0 = expf(p2 - smax), e1 = expf(p3 - smax), e2 = expf(p4 - smax);
    float einv = 1.f / (e0 + e1 + e2);
    float s0 = e0 * einv, s1 = e1 * einv, s2 = e2 * einv;
    float gamma = 1.f + softplusf_(pp[MM + 5]);

    float d0 = 0.f, d1 = 0.f, d2 = 0.f, d3 = 0.f;
    float q0 = 0.f, q1 = 0.f, q2 = 0.f, q3 = 0.f;
    const int base = tid * MM;
    #pragma unroll 4
    for (int j = 0; j < MM; j += 4) {
        int m0 = (j + 0 + tid) & (MM - 1);
        int m1 = (j + 1 + tid) & (MM - 1);
        int m2 = (j + 2 + tid) & (MM - 1);
        int m3 = (j + 3 + tid) & (MM - 1);
        float v0 = s_mem[base + m0], v1 = s_mem[base + m1];
        float v2 = s_mem[base + m2], v3 = s_mem[base + m3];
        d0 += pp[m0] * v0; q0 += v0 * v0;
        d1 += pp[m1] * v1; q1 += v1 * v1;
        d2 += pp[m2] * v2; q2 += v2 * v2;
        d3 += pp[m3] * v3; q3 += v3 * v3;
    }
    float dot = (d0 + d1) + (d2 + d3);
    float msq = (q0 + q1) + (q2 + q3);
    float sim = dot / (knorm * sqrtf(msq) + EPSF);

    float z = beta * sim;
    float zmax = block_max(z, r8x4 + 8, tid);
    float ez = expf(z - zmax);
    float zsum = block_sum(ez, r8x4 + 16, tid);
    float wc = ez / zsum;

    float wprev = sw_state[tid];
    float wg = gg * wc + (1.f - gg) * wprev;
    s_w[tid] = wg;
    __syncthreads();

    float wt = s_w[(tid + 1) & (NN - 1)] * s0 + wg * s1 + s_w[(tid + NN - 1) & (NN - 1)] * s2;
    float wp = powf(wt + EPSF, gamma);
    float wsum = block_sum(wp, r8x4 + 24, tid);
    float wn = wp / wsum;
    s_w[tid] = wn;
    sw_state[tid] = wn;
    __syncthreads();
}

// ============================================================================
// Persistent kernel. dyn smem:
//   [0, 131072)        NTM memory tile (fp32, resident all steps)
//   [131072, 196608)   phase-B bf16 tiles (4 x 16 KB) — phase A aliases this
// ============================================================================
extern __shared__ __align__(1024) float dyn[];

__global__ void __launch_bounds__(256, 1) ntm_persistent_kernel(
    const float* __restrict__ Wc, const float* __restrict__ bc,
    const float* __restrict__ mem_init, const float* __restrict__ read_init,
    float* __restrict__ out)
{
    float* s_mem = dyn;
    float* gsm = dyn + NN * MM;          // phase A FFMA2 buffers (alias of B tiles)
    char* tiles = (char*)(dyn) + 131072; // phase B bf16 tiles

    const int cta = blockIdx.x;
    const int tid = threadIdx.x;
    const int wid = tid >> 5;
    const int lane = tid & 31;
    const int tx = tid & 15;
    const int ty = tid >> 4;

    __shared__ float s_p[PR + PWD];
    __shared__ float s_w[NN], s_red[NN], s_r8[32], s_e[MM], s_a[MM];
    __shared__ float s_wr[NN], s_ww[NN];

    // state init
    if (cta < BB) {
        const float4* mi = (const float4*)mem_init;
        float4* sm4 = (float4*)s_mem;
        for (int i = tid; i < NN * MM / 4; i += 256) sm4[i] = mi[i];
        for (int i = tid; i < NN; i += 256) { s_wr[i] = 1.f / NN; s_ww[i] = 1.f / NN; }
        if (tid < MM) g_r[cta * MM + tid] = read_init[tid];
    }
    grid_barrier();

    #define AH(buf,k,j) gsm[(buf)*576 + (k)*36 + (j)]
    #define BH(buf,k,j) gsm[1152 + (buf)*2112 + (k)*132 + (j)]

    // phase B constants
    const int tilec = cta % 9;
    const int zz = cta / 9;
    const int col0B = tilec * 128;
    const int kbaseB = zz * 128;
    const uint32_t tAhi = s2u(tiles);
    const uint32_t tAlo = tAhi + 16384;
    const uint32_t tBhi = tAhi + 32768;
    const uint32_t tBlo = tAhi + 49152;

    // mma lane constants
    const int mrow = (wid & 3) * 32;       // warp row group (4 x 32 rows)
    const int ncol = (wid >> 2) * 64;      // warp col group (2 x 64 cols)
    const int aRow = lane & 15;
    const int aG   = lane >> 4;            // 0/1 -> k-half
    const int bRow = ((lane >> 4) << 3) + (lane & 7);
    const int bG   = (lane >> 3) & 1;

    for (int t = 0; t < TT; t++) {
        // ---------------- phase A: h = tanh(r @ Wc[0:128] + xproj + bc) ------
        if (cta < 128) {
            const int row0 = (cta >> 4) * 16;
            const int col0 = (cta & 15) * 128;
            const int am = tid >> 4, akk = tid & 15;
            const int bkr = tid >> 5, bn4 = (tid & 31) << 2;

            float avr = g_r[(row0 + am) * MM + akk];
            float4 bvr0 = *(const float4*)(Wc + (size_t)bkr * CC + col0 + bn4);
            float4 bvr1 = *(const float4*)(Wc + (size_t)(bkr + 8) * CC + col0 + bn4);
            *(float2*)&AH(0, akk, 2 * am) = make_float2(avr, avr);
            *(float4*)&BH(0, bkr, bn4) = bvr0;
            *(float4*)&BH(0, bkr + 8, bn4) = bvr1;
            __syncthreads();

            ull acc[4] = {0, 0, 0, 0};
            for (int kt = 0; kt < 8; kt++) {
                int cur = kt & 1;
                if (kt < 7) {
                    int k0 = (kt + 1) * 16;
                    avr = g_r[(row0 + am) * MM + k0 + akk];
                    bvr0 = *(const float4*)(Wc + (size_t)(k0 + bkr) * CC + col0 + bn4);
                    bvr1 = *(const float4*)(Wc + (size_t)(k0 + bkr + 8) * CC + col0 + bn4);
                }
                #pragma unroll
                for (int kk = 0; kk < 16; kk++) {
                    ull a2 = *(const ull*)&AH(cur, kk, ty * 2);
                    ulonglong2 b01 = *(const ulonglong2*)&BH(cur, kk, tx * 4);
                    ulonglong2 b23 = *(const ulonglong2*)&BH(cur, kk, 64 + tx * 4);
                    FFMA2(acc[0], a2, b01.x, acc[0]);
                    FFMA2(acc[1], a2, b01.y, acc[1]);
                    FFMA2(acc[2], a2, b23.x, acc[2]);
                    FFMA2(acc[3], a2, b23.y, acc[3]);
                }
                if (kt < 7) {
                    int nxt = cur ^ 1;
                    *(float2*)&AH(nxt, akk, 2 * am) = make_float2(avr, avr);
                    *(float4*)&BH(nxt, bkr, bn4) = bvr0;
                    *(float4*)&BH(nxt, bkr + 8, bn4) = bvr1;
                    __syncthreads();
                }
            }
            {
                int m = row0 + ty;
                const float* xp = g_xproj + ((size_t)t * BB + m) * CC + col0;
                float4 x0 = *(const float4*)(xp + tx * 4);
                float4 x1 = *(const float4*)(xp + 64 + tx * 4);
                float4 b0 = *(const float4*)(bc + col0 + tx * 4);
                float4 b1 = *(const float4*)(bc + col0 + 64 + tx * 4);
                float2 p0 = ull2f2(acc[0]), p1 = ull2f2(acc[1]);
                float2 p2 = ull2f2(acc[2]), p3 = ull2f2(acc[3]);
                float hv[8];
                hv[0] = tanhf(p0.x + x0.x + b0.x);
                hv[1] = tanhf(p0.y + x0.y + b0.y);
                hv[2] = tanhf(p1.x + x0.z + b0.z);
                hv[3] = tanhf(p1.y + x0.w + b0.w);
                hv[4] = tanhf(p2.x + x1.x + b1.x);
                hv[5] = tanhf(p2.y + x1.y + b1.y);
                hv[6] = tanhf(p3.x + x1.z + b1.z);
                hv[7] = tanhf(p3.y + x1.w + b1.w);
                __nv_bfloat16 hb[8], lb[8];
                #pragma unroll
                for (int i = 0; i < 8; i++) {
                    hb[i] = __float2bfloat16_rn(hv[i]);
                    lb[i] = __float2bfloat16_rn(hv[i] - __bfloat162float(hb[i]));
                }
                size_t base = (size_t)m * CC + col0;
                *(uint2*)(g_hhi + base + tx * 4)      = *(uint2*)&hb[0];
                *(uint2*)(g_hhi + base + 64 + tx * 4) = *(uint2*)&hb[4];
                *(uint2*)(g_hlo + base + tx * 4)      = *(uint2*)&lb[0];
                *(uint2*)(g_hlo + base + 64 + tx * 4) = *(uint2*)&lb[4];
            }
        }
        grid_barrier();

        // ---------------- phase B: HMMA bf16 3-pass GEMM ----------------------
        {
            float acc[2][8][4];
            #pragma unroll
            for (int i = 0; i < 2; i++)
                #pragma unroll
                for (int j = 0; j < 8; j++)
                    #pragma unroll
                    for (int k = 0; k < 4; k++) acc[i][j][k] = 0.f;

            for (int ch = 0; ch < 2; ch++) {
                const int k0 = kbaseB + ch * 64;
                // stage 4 tiles: [128 rows][64 k] bf16 = 16 KB each, XOR-swizzled
                #pragma unroll
                for (int i = 0; i < 4; i++) {
                    int idx = tid + i * 256;          // 0..1023
                    int r = idx >> 3, gq = idx & 7;   // row, 16B-chunk
                    uint32_t so = swz128((uint32_t)(r * 128 + gq * 16));
                    const char* ahp = (const char*)(g_hhi + (size_t)r * CC + k0) + gq * 16;
                    const char* alp = (const char*)(g_hlo + (size_t)r * CC + k0) + gq * 16;
                    const char* bhp = (const char*)(g_wthi + (size_t)(col0B + r) * CC + k0) + gq * 16;
                    const char* blp = (const char*)(g_wtlo + (size_t)(col0B + r) * CC + k0) + gq * 16;
                    *(uint4*)(tiles + 0     + so) = *(const uint4*)ahp;
                    *(uint4*)(tiles + 16384 + so) = *(const uint4*)alp;
                    *(uint4*)(tiles + 32768 + so) = *(const uint4*)bhp;
                    *(uint4*)(tiles + 49152 + so) = *(const uint4*)blp;
                }
                __syncthreads();

                #pragma unroll
                for (int ks = 0; ks < 4; ks++) {
                    uint32_t ahi[2][4], alo[2][4];
                    #pragma unroll
                    for (int mf = 0; mf < 2; mf++) {
                        uint32_t off = swz128((uint32_t)((mrow + 16 * mf + aRow) * 128
                                                         + (2 * ks + aG) * 16));
                        LDSM_X4(ahi[mf], tAhi + off);
                        LDSM_X4(alo[mf], tAlo + off);
                    }
                    #pragma unroll
                    for (int nq = 0; nq < 4; nq++) {
                        uint32_t off = swz128((uint32_t)((ncol + 16 * nq + bRow) * 128
                                                         + (2 * ks + bG) * 16));
                        uint32_t bh[4], bl[4];
                        LDSM_X4(bh, tBhi + off);
                        LDSM_X4(bl, tBlo + off);
                        #pragma unroll
                        for (int mf = 0; mf < 2; mf++) {
                            MMA_BF16(acc[mf][2 * nq + 0], ahi[mf], bh[0], bh[1]);
                            MMA_BF16(acc[mf][2 * nq + 0], ahi[mf], bl[0], bl[1]);
                            MMA_BF16(acc[mf][2 * nq + 0], alo[mf], bh[0], bh[1]);
                            MMA_BF16(acc[mf][2 * nq + 1], ahi[mf], bh[2], bh[3]);
                            MMA_BF16(acc[mf][2 * nq + 1], ahi[mf], bl[2], bl[3]);
                            MMA_BF16(acc[mf][2 * nq + 1], alo[mf], bh[2], bh[3]);
                        }
                    }
                }
                __syncthreads();   // before restaging / phase A alias next step
            }

            // epilogue: write 128x128 fp32 tile to g_pp[zz]
            // row = mrow + 16*mf + lane/4 (+8), col = col0B + ncol + nb*8 + (lane%4)*2
            float* pq = g_pp + (size_t)zz * BB * PDIMP;
            #pragma unroll
            for (int mf = 0; mf < 2; mf++) {
                int r0 = mrow + 16 * mf + (lane >> 2);
                #pragma unroll
                for (int nb = 0; nb < 8; nb++) {
                    int c = col0B + ncol + nb * 8 + (lane & 3) * 2;
                    *(float2*)(pq + (size_t)r0 * PDIMP + c) =
                        make_float2(acc[mf][nb][0], acc[mf][nb][1]);
                    *(float2*)(pq + (size_t)(r0 + 8) * PDIMP + c) =
                        make_float2(acc[mf][nb][2], acc[mf][nb][3]);
                }
            }
        }
        grid_barrier();

        // ---------------- phase C: NTM step -----------------------------------
        if (cta < BB) {
            const int b = cta;

            for (int i = tid; i < PR + PWD; i += 256) {
                float s = g_ball[i];
                #pragma unroll
                for (int ks = 0; ks < SK; ks++)
                    s += g_pp[(size_t)ks * BB * PDIMP + (size_t)b * PDIMP + i];
                s_p[i] = s;
            }
            {
                int c = tid * 2;
                if (c < OUTD) {
                    float v0 = g_ball[PR + PWD + c];
                    float v1 = g_ball[PR + PWD + c + 1];
                    #pragma unroll
                    for (int ks = 0; ks < SK; ks++) {
                        const float* pq = g_pp + (size_t)ks * BB * PDIMP + (size_t)b * PDIMP + PR + PWD + c;
                        v0 += pq[0]; v1 += pq[1];
                    }
                    float* o = out + ((long long)b * TT + t) * OUTD + c;
                    o[0] = v0; o[1] = v1;
                }
            }
            __syncthreads();
            if (tid < MM) {
                s_e[tid] = sigmoidf_(s_p[PR + PR + tid]);
                s_a[tid] = tanhf(s_p[PR + 2 * MM + 6 + tid]);
            }
            __syncthreads();

            address_fn(s_p, s_wr, s_mem, s_w, s_r8, tid);

            {
                int m = tid & (MM - 1);
                int half = tid >> 7;
                int n0 = half * 128;
                float a0 = 0.f, a1 = 0.f, a2 = 0.f, a3 = 0.f;
                #pragma unroll 4
                for (int n = n0; n < n0 + 128; n += 4) {
                    a0 += s_w[n + 0] * s_mem[(n + 0) * MM + m];
                    a1 += s_w[n + 1] * s_mem[(n + 1) * MM + m];
                    a2 += s_w[n + 2] * s_mem[(n + 2) * MM + m];
                    a3 += s_w[n + 3] * s_mem[(n + 3) * MM + m];
                }
                s_red[tid] = (a0 + a1) + (a2 + a3);
                __syncthreads();
                if (tid < MM) g_r[b * MM + tid] = s_red[tid] + s_red[tid + 128];
                __syncthreads();
            }

            address_fn(s_p + PR, s_ww, s_mem, s_w, s_r8, tid);

            {
                float4* sm4 = (float4*)s_mem;
                const float4* e4 = (const float4*)s_e;
                const float4* a4 = (const float4*)s_a;
                #pragma unroll 4
                for (int i = tid; i < NN * MM / 4; i += 256) {
                    int n = i >> 5;
                    int m4 = i & 31;
                    float wwn = s_w[n];
                    float4 old = sm4[i];
                    float4 ev = e4[m4];
                    float4 av = a4[m4];
                    float4 r;
                    r.x = old.x * (1.f - wwn * ev.x) + wwn * av.x;
                    r.y = old.y * (1.f - wwn * ev.y) + wwn * av.y;
                    r.z = old.z * (1.f - wwn * ev.z) + wwn * av.z;
                    r.w = old.w * (1.f - wwn * ev.w) + wwn * av.w;
                    sm4[i] = r;
                }
            }
        }
        grid_barrier();
    }
}

// -------- launch --------
extern "C" void kernel_launch(void* const* d_in, const int* in_sizes, int n_in,
                              void* d_out, int out_size) {
    const float* x        = (const float*)d_in[0];
    const float* Wc       = (const float*)d_in[1];
    const float* bc       = (const float*)d_in[2];
    const float* Wout     = (const float*)d_in[3];
    const float* bout     = (const float*)d_in[4];
    const float* Wr       = (const float*)d_in[5];
    const float* br       = (const float*)d_in[6];
    const float* Ww       = (const float*)d_in[7];
    const float* bw       = (const float*)d_in[8];
    const float* mem_init = (const float*)d_in[9];
    const float* read_init= (const float*)d_in[10];
    float* out = (float*)d_out;
    (void)in_sizes; (void)n_in; (void)out_size;

    const int DYNSMEM = 131072 + 65536;  // 196608 B
    cudaFuncSetAttribute(ntm_persistent_kernel,
                         cudaFuncAttributeMaxDynamicSharedMemorySize, DYNSMEM);

    pack_w_kernel<<<512, 256>>>(Wr, br, Ww, bw, Wout, bout);

    dim3 thr(16, 16);
    dim3 grid_x(CC / 128, (BB * TT) / 64);
    xproj_kernel<<<grid_x, thr>>>(x, Wc);

    ntm_persistent_kernel<<<NCTA, 256, DYNSMEM>>>(Wc, bc, mem_init, read_init, out);
}

// round 10
// speedup vs baseline: 3.6800x; 1.0131x over previous
#include <cuda_runtime.h>
#include <cuda_bf16.h>
#include <math.h>
#include <stdint.h>

#define BB 128
#define TT 256
#define INDIM 512
#define CC 2048
#define NN 256
#define MM 128
#define OUTD 512
#define PR 134            // M+6
#define PWD 390           // 3M+6
#define PDIM 1036         // PR + PWD + OUTD
#define PDIMP 1152        // 9*128 col tiles
#define SK 16             // split-K for phase B (9 coltiles * 16 = 144 jobs)
#define NCTA 144
#define EPSF 1e-8f

typedef unsigned long long ull;

// -------- persistent device state --------
__device__ float g_pp[SK*BB*PDIMP];                       // split-K partials
__device__ float g_r[BB*MM];
__device__ __align__(16) __nv_bfloat16 g_hhi[BB*CC];      // h split hi/lo (row-major)
__device__ __align__(16) __nv_bfloat16 g_hlo[BB*CC];
__device__ __align__(16) __nv_bfloat16 g_wthi[PDIMP*CC];  // Wall^T split hi/lo: [n][k]
__device__ __align__(16) __nv_bfloat16 g_wtlo[PDIMP*CC];
__device__ __align__(16) float g_ball[PDIM];
__device__ float g_xproj[(size_t)TT*BB*CC];               // [t][b][c]
__device__ unsigned g_bar_cnt;
__device__ unsigned g_bar_gen;

// -------- f32x2 FMA --------
#define FFMA2(d, a, b, c) \
    asm("fma.rn.f32x2 %0, %1, %2, %3;" : "=l"(d) : "l"(a), "l"(b), "l"(c))

__device__ __forceinline__ float2 ull2f2(ull v) {
    float2 r;
    r.x = __uint_as_float((unsigned)(v & 0xffffffffULL));
    r.y = __uint_as_float((unsigned)(v >> 32));
    return r;
}

__device__ __forceinline__ float sigmoidf_(float x) { return 1.f / (1.f + expf(-x)); }
__device__ __forceinline__ float softplusf_(float x) {
    return fmaxf(x, 0.f) + log1pf(expf(-fabsf(x)));
}

// -------- mma.sync / ldmatrix helpers (plain sm_103, no 'a' features) --------
__device__ __forceinline__ uint32_t s2u(const void* p) {
    uint32_t a;
    asm("{ .reg .u64 t; cvta.to.shared.u64 t, %1; cvt.u32.u64 %0, t; }" : "=r"(a) : "l"(p));
    return a;
}
__device__ __forceinline__ uint32_t swz128(uint32_t o) { return o ^ ((o >> 3) & 0x70); }

#define LDSM_X4(r, addr) \
    asm volatile("ldmatrix.sync.aligned.m8n8.x4.shared.b16 {%0,%1,%2,%3}, [%4];" \
        : "=r"((r)[0]), "=r"((r)[1]), "=r"((r)[2]), "=r"((r)[3]) : "r"(addr))

#define MMA_BF16(d, a, b0_, b1_) \
    asm volatile("mma.sync.aligned.m16n8k16.row.col.f32.bf16.bf16.f32 " \
        "{%0,%1,%2,%3}, {%4,%5,%6,%7}, {%8,%9}, {%0,%1,%2,%3};" \
        : "+f"((d)[0]), "+f"((d)[1]), "+f"((d)[2]), "+f"((d)[3]) \
        : "r"((a)[0]), "r"((a)[1]), "r"((a)[2]), "r"((a)[3]), "r"(b0_), "r"(b1_))

// -------- software grid barrier (144 CTAs, 1/SM, all resident) --------
// Backoff spin: tight ld.acquire polling from 143 CTAs on one L2 line both
// delays the release store and steals L2 BW from the working phase.
__device__ __forceinline__ void grid_barrier() {
    __syncthreads();
    if (threadIdx.x == 0) {
        __threadfence();
        unsigned gen;
        asm volatile("ld.acquire.gpu.u32 %0, [%1];" : "=r"(gen) : "l"(&g_bar_gen) : "memory");
        if (atomicAdd(&g_bar_cnt, 1u) == NCTA - 1) {
            atomicExch(&g_bar_cnt, 0u);
            __threadfence();
            atomicExch(&g_bar_gen, gen + 1u);
        } else {
            unsigned cur;
            unsigned ns = 32;
            do {
                __nanosleep(ns);
                if (ns < 256) ns <<= 1;
                asm volatile("ld.acquire.gpu.u32 %0, [%1];" : "=r"(cur) : "l"(&g_bar_gen) : "memory");
            } while (cur == gen);
        }
    }
    __syncthreads();
}

// -------- init: pack transposed bf16 hi/lo weights + bias --------
__global__ void pack_w_kernel(const float* __restrict__ Wr, const float* __restrict__ br,
                              const float* __restrict__ Ww, const float* __restrict__ bw,
                              const float* __restrict__ Wout, const float* __restrict__ bout) {
    int gid = blockIdx.x * blockDim.x + threadIdx.x;
    int stride = gridDim.x * blockDim.x;
    for (int i = gid; i < PDIM; i += stride) {
        float v;
        if (i < PR) v = br[i];
        else if (i < PR + PWD) v = bw[i - PR];
        else v = bout[i - PR - PWD];
        g_ball[i] = v;
    }
    int total = PDIMP * CC;
    for (int idx = gid; idx < total; idx += stride) {
        int n = idx / CC, k = idx % CC;
        float v = 0.f;
        if (n < PR) v = Wr[k * PR + n];
        else if (n < PR + PWD) v = Ww[k * PWD + (n - PR)];
        else if (n < PDIM) v = Wout[k * OUTD + (n - PR - PWD)];
        __nv_bfloat16 hi = __float2bfloat16_rn(v);
        g_wthi[idx] = hi;
        g_wtlo[idx] = __float2bfloat16_rn(v - __bfloat162float(hi));
    }
}

// -------- xproj = x[B*T, 512] @ Wc[128:640, :]  -> [t][b][c] --------
__global__ void __launch_bounds__(256, 2) xproj_kernel(const float* __restrict__ x,
                                                       const float* __restrict__ Wc) {
    __shared__ __align__(16) float As2[2][16][132];
    __shared__ __align__(16) float Bs[2][16][132];
    const int tx = threadIdx.x, ty = threadIdx.y;
    const int tid = ty * 16 + tx;
    const long long row0 = (long long)blockIdx.y * 64;
    const int col0 = blockIdx.x * 128;

    const int am = tid >> 2;
    const int akq = (tid & 3) << 2;
    const int bkr = tid >> 5;
    const int bn4 = (tid & 31) << 2;

    const int KT = INDIM / 16;
    float4 avr, bvr0, bvr1;

    {
        avr = *(const float4*)(x + (row0 + am) * INDIM + akq);
        bvr0 = *(const float4*)(Wc + (size_t)(MM + bkr) * CC + col0 + bn4);
        bvr1 = *(const float4*)(Wc + (size_t)(MM + bkr + 8) * CC + col0 + bn4);
        *(float2*)&As2[0][akq + 0][2 * am] = make_float2(avr.x, avr.x);
        *(float2*)&As2[0][akq + 1][2 * am] = make_float2(avr.y, avr.y);
        *(float2*)&As2[0][akq + 2][2 * am] = make_float2(avr.z, avr.z);
        *(float2*)&As2[0][akq + 3][2 * am] = make_float2(avr.w, avr.w);
        *(float4*)&Bs[0][bkr][bn4] = bvr0;
        *(float4*)&Bs[0][bkr + 8][bn4] = bvr1;
    }
    __syncthreads();

    ull acc[4][4] = {{0,0,0,0},{0,0,0,0},{0,0,0,0},{0,0,0,0}};

    for (int kt = 0; kt < KT; kt++) {
        int cur = kt & 1;
        if (kt + 1 < KT) {
            int k0 = (kt + 1) * 16;
            avr = *(const float4*)(x + (row0 + am) * INDIM + k0 + akq);
            bvr0 = *(const float4*)(Wc + (size_t)(MM + k0 + bkr) * CC + col0 + bn4);
            bvr1 = *(const float4*)(Wc + (size_t)(MM + k0 + bkr + 8) * CC + col0 + bn4);
        }
        #pragma unroll
        for (int kk = 0; kk < 16; kk++) {
            ulonglong2 a01 = *(const ulonglong2*)&As2[cur][kk][ty * 8];
            ulonglong2 a23 = *(const ulonglong2*)&As2[cur][kk][ty * 8 + 4];
            ulonglong2 b01 = *(const ulonglong2*)&Bs[cur][kk][tx * 4];
            ulonglong2 b23 = *(const ulonglong2*)&Bs[cur][kk][64 + tx * 4];
            ull av[4] = {a01.x, a01.y, a23.x, a23.y};
            ull bv[4] = {b01.x, b01.y, b23.x, b23.y};
            #pragma unroll
            for (int i = 0; i < 4; i++)
                #pragma unroll
                for (int j = 0; j < 4; j++)
                    FFMA2(acc[i][j], av[i], bv[j], acc[i][j]);
        }
        if (kt + 1 < KT) {
            int nxt = cur ^ 1;
            *(float2*)&As2[nxt][akq + 0][2 * am] = make_float2(avr.x, avr.x);
            *(float2*)&As2[nxt][akq + 1][2 * am] = make_float2(avr.y, avr.y);
            *(float2*)&As2[nxt][akq + 2][2 * am] = make_float2(avr.z, avr.z);
            *(float2*)&As2[nxt][akq + 3][2 * am] = make_float2(avr.w, avr.w);
            *(float4*)&Bs[nxt][bkr][bn4] = bvr0;
            *(float4*)&Bs[nxt][bkr + 8][bn4] = bvr1;
            __syncthreads();
        }
    }

    #pragma unroll
    for (int i = 0; i < 4; i++) {
        long long rid = row0 + ty * 4 + i;
        int bb = (int)(rid >> 8);
        int tt = (int)(rid & 255);
        float* dst = g_xproj + ((size_t)tt * BB + bb) * CC + col0;
        float2 p0 = ull2f2(acc[i][0]), p1 = ull2f2(acc[i][1]);
        float2 p2 = ull2f2(acc[i][2]), p3 = ull2f2(acc[i][3]);
        *(float4*)(dst + tx * 4)      = make_float4(p0.x, p0.y, p1.x, p1.y);
        *(float4*)(dst + 64 + tx * 4) = make_float4(p2.x, p2.y, p3.x, p3.y);
    }
}

// -------- block reductions --------
__device__ __forceinline__ float warp_red_sum(float v) {
    #pragma unroll
    for (int o = 16; o; o >>= 1) v += __shfl_xor_sync(0xffffffffu, v, o);
    return v;
}
__device__ __forceinline__ float warp_red_max(float v) {
    #pragma unroll
    for (int o = 16; o; o >>= 1) v = fmaxf(v, __shfl_xor_sync(0xffffffffu, v, o));
    return v;
}
__device__ __forceinline__ float block_sum(float v, float* r8, int tid) {
    v = warp_red_sum(v);
    if ((tid & 31) == 0) r8[tid >> 5] = v;
    __syncthreads();
    float s = 0.f;
    #pragma unroll
    for (int i = 0; i < 8; i++) s += r8[i];
    return s;
}
__device__ __forceinline__ float block_max(float v, float* r8, int tid) {
    v = warp_red_max(v);
    if ((tid & 31) == 0) r8[tid >> 5] = v;
    __syncthreads();
    float s = r8[0];
    #pragma unroll
    for (int i = 1; i < 8; i++) s = fmaxf(s, r8[i]);
    return s;
}

__device__ void address_fn(const float* __restrict__ pp, float* __restrict__ sw_state,
                           const float* __restrict__ s_mem,
                           float* __restrict__ s_w, float* __restrict__ r8x4, int tid) {
    float kv = (tid < MM) ? pp[tid] : 0.f;
    float knorm = sqrtf(block_sum(kv * kv, r8x4 + 0, tid));
    float beta  = softplusf_(pp[MM]);
    float gg    = sigmoidf_(pp[MM + 1]);
    float p2 = pp[MM + 2], p3 = pp[MM + 3], p4 = pp[MM + 4];
    float smax = fmaxf(p2, fmaxf(p3, p4));
    float e0 = expf(p2 - smax), e1 = expf(p3 - smax), e2 = expf(p4 - smax);
    float einv = 1.f / (e0 + e1 + e2);
    float s0 = e0 * einv, s1 = e1 * einv, s2 = e2 * einv;
    float gamma = 1.f + softplusf_(pp[MM + 5]);

    float d0 = 0.f, d1 = 0.f, d2 = 0.f, d3 = 0.f;
    float q0 = 0.f, q1 = 0.f, q2 = 0.f, q3 = 0.f;
    const int base = tid * MM;
    #pragma unroll 4
    for (int j = 0; j < MM; j += 4) {
        int m0 = (j + 0 + tid) & (MM - 1);
        int m1 = (j + 1 + tid) & (MM - 1);
        int m2 = (j + 2 + tid) & (MM - 1);
        int m3 = (j + 3 + tid) & (MM - 1);
        float v0 = s_mem[base + m0], v1 = s_mem[base + m1];
        float v2 = s_mem[base + m2], v3 = s_mem[base + m3];
        d0 += pp[m0] * v0; q0 += v0 * v0;
        d1 += pp[m1] * v1; q1 += v1 * v1;
        d2 += pp[m2] * v2; q2 += v2 * v2;
        d3 += pp[m3] * v3; q3 += v3 * v3;
    }
    float dot = (d0 + d1) + (d2 + d3);
    float msq = (q0 + q1) + (q2 + q3);
    float sim = dot / (knorm * sqrtf(msq) + EPSF);

    float z = beta * sim;
    float zmax = block_max(z, r8x4 + 8, tid);
    float ez = expf(z - zmax);
    float zsum = block_sum(ez, r8x4 + 16, tid);
    float wc = ez / zsum;

    float wprev = sw_state[tid];
    float wg = gg * wc + (1.f - gg) * wprev;
    s_w[tid] = wg;
    __syncthreads();

    float wt = s_w[(tid + 1) & (NN - 1)] * s0 + wg * s1 + s_w[(tid + NN - 1) & (NN - 1)] * s2;
    float wp = powf(wt + EPSF, gamma);
    float wsum = block_sum(wp, r8x4 + 24, tid);
    float wn = wp / wsum;
    s_w[tid] = wn;
    sw_state[tid] = wn;
    __syncthreads();
}

// ============================================================================
// Persistent kernel. dyn smem:
//   [0, 131072)        NTM memory tile (fp32, resident all steps)
//   [131072, 196608)   phase-B bf16 tiles (4 x 16 KB) — phase A aliases this
// ============================================================================
extern __shared__ __align__(1024) float dyn[];

__global__ void __launch_bounds__(256, 1) ntm_persistent_kernel(
    const float* __restrict__ Wc, const float* __restrict__ bc,
    const float* __restrict__ mem_init, const float* __restrict__ read_init,
    float* __restrict__ out)
{
    float* s_mem = dyn;
    float* gsm = dyn + NN * MM;          // phase A FFMA2 buffers (alias of B tiles)
    char* tiles = (char*)(dyn) + 131072; // phase B bf16 tiles

    const int cta = blockIdx.x;
    const int tid = threadIdx.x;
    const int wid = tid >> 5;
    const int lane = tid & 31;
    const int tx = tid & 15;
    const int ty = tid >> 4;

    __shared__ __align__(16) float s_p[PR + PWD];
    __shared__ float s_w[NN], s_red[NN], s_r8[32], s_e[MM], s_a[MM];
    __shared__ float s_wr[NN], s_ww[NN];

    // state init
    if (cta < BB) {
        const float4* mi = (const float4*)mem_init;
        float4* sm4 = (float4*)s_mem;
        for (int i = tid; i < NN * MM / 4; i += 256) sm4[i] = mi[i];
        for (int i = tid; i < NN; i += 256) { s_wr[i] = 1.f / NN; s_ww[i] = 1.f / NN; }
        if (tid < MM) g_r[cta * MM + tid] = read_init[tid];
    }
    grid_barrier();

    #define AH(buf,k,j) gsm[(buf)*576 + (k)*36 + (j)]
    #define BH(buf,k,j) gsm[1152 + (buf)*2112 + (k)*132 + (j)]

    // phase B constants
    const int tilec = cta % 9;
    const int zz = cta / 9;
    const int col0B = tilec * 128;
    const int kbaseB = zz * 128;
    const uint32_t tAhi = s2u(tiles);
    const uint32_t tAlo = tAhi + 16384;
    const uint32_t tBhi = tAhi + 32768;
    const uint32_t tBlo = tAhi + 49152;

    // mma lane constants
    const int mrow = (wid & 3) * 32;       // warp row group (4 x 32 rows)
    const int ncol = (wid >> 2) * 64;      // warp col group (2 x 64 cols)
    const int aRow = lane & 15;
    const int aG   = lane >> 4;            // 0/1 -> k-half
    const int bRow = ((lane >> 4) << 3) + (lane & 7);
    const int bG   = (lane >> 3) & 1;

    for (int t = 0; t < TT; t++) {
        // ---------------- phase A: h = tanh(r @ Wc[0:128] + xproj + bc) ------
        if (cta < 128) {
            const int row0 = (cta >> 4) * 16;
            const int col0 = (cta & 15) * 128;
            const int am = tid >> 4, akk = tid & 15;
            const int bkr = tid >> 5, bn4 = (tid & 31) << 2;

            float avr = g_r[(row0 + am) * MM + akk];
            float4 bvr0 = *(const float4*)(Wc + (size_t)bkr * CC + col0 + bn4);
            float4 bvr1 = *(const float4*)(Wc + (size_t)(bkr + 8) * CC + col0 + bn4);
            *(float2*)&AH(0, akk, 2 * am) = make_float2(avr, avr);
            *(float4*)&BH(0, bkr, bn4) = bvr0;
            *(float4*)&BH(0, bkr + 8, bn4) = bvr1;
            __syncthreads();

            ull acc[4] = {0, 0, 0, 0};
            for (int kt = 0; kt < 8; kt++) {
                int cur = kt & 1;
                if (kt < 7) {
                    int k0 = (kt + 1) * 16;
                    avr = g_r[(row0 + am) * MM + k0 + akk];
                    bvr0 = *(const float4*)(Wc + (size_t)(k0 + bkr) * CC + col0 + bn4);
                    bvr1 = *(const float4*)(Wc + (size_t)(k0 + bkr + 8) * CC + col0 + bn4);
                }
                #pragma unroll
                for (int kk = 0; kk < 16; kk++) {
                    ull a2 = *(const ull*)&AH(cur, kk, ty * 2);
                    ulonglong2 b01 = *(const ulonglong2*)&BH(cur, kk, tx * 4);
                    ulonglong2 b23 = *(const ulonglong2*)&BH(cur, kk, 64 + tx * 4);
                    FFMA2(acc[0], a2, b01.x, acc[0]);
                    FFMA2(acc[1], a2, b01.y, acc[1]);
                    FFMA2(acc[2], a2, b23.x, acc[2]);
                    FFMA2(acc[3], a2, b23.y, acc[3]);
                }
                if (kt < 7) {
                    int nxt = cur ^ 1;
                    *(float2*)&AH(nxt, akk, 2 * am) = make_float2(avr, avr);
                    *(float4*)&BH(nxt, bkr, bn4) = bvr0;
                    *(float4*)&BH(nxt, bkr + 8, bn4) = bvr1;
                    __syncthreads();
                }
            }
            {
                int m = row0 + ty;
                const float* xp = g_xproj + ((size_t)t * BB + m) * CC + col0;
                float4 x0 = *(const float4*)(xp + tx * 4);
                float4 x1 = *(const float4*)(xp + 64 + tx * 4);
                float4 b0 = *(const float4*)(bc + col0 + tx * 4);
                float4 b1 = *(const float4*)(bc + col0 + 64 + tx * 4);
                float2 p0 = ull2f2(acc[0]), p1 = ull2f2(acc[1]);
                float2 p2 = ull2f2(acc[2]), p3 = ull2f2(acc[3]);
                float hv[8];
                hv[0] = tanhf(p0.x + x0.x + b0.x);
                hv[1] = tanhf(p0.y + x0.y + b0.y);
                hv[2] = tanhf(p1.x + x0.z + b0.z);
                hv[3] = tanhf(p1.y + x0.w + b0.w);
                hv[4] = tanhf(p2.x + x1.x + b1.x);
                hv[5] = tanhf(p2.y + x1.y + b1.y);
                hv[6] = tanhf(p3.x + x1.z + b1.z);
                hv[7] = tanhf(p3.y + x1.w + b1.w);
                __nv_bfloat16 hb[8], lb[8];
                #pragma unroll
                for (int i = 0; i < 8; i++) {
                    hb[i] = __float2bfloat16_rn(hv[i]);
                    lb[i] = __float2bfloat16_rn(hv[i] - __bfloat162float(hb[i]));
                }
                size_t base = (size_t)m * CC + col0;
                *(uint2*)(g_hhi + base + tx * 4)      = *(uint2*)&hb[0];
                *(uint2*)(g_hhi + base + 64 + tx * 4) = *(uint2*)&hb[4];
                *(uint2*)(g_hlo + base + tx * 4)      = *(uint2*)&lb[0];
                *(uint2*)(g_hlo + base + 64 + tx * 4) = *(uint2*)&lb[4];
            }
        }
        grid_barrier();

        // ---------------- phase B: HMMA bf16 3-pass GEMM ----------------------
        {
            float acc[2][8][4];
            #pragma unroll
            for (int i = 0; i < 2; i++)
                #pragma unroll
                for (int j = 0; j < 8; j++)
                    #pragma unroll
                    for (int k = 0; k < 4; k++) acc[i][j][k] = 0.f;

            for (int ch = 0; ch < 2; ch++) {
                const int k0 = kbaseB + ch * 64;
                // stage 4 tiles: [128 rows][64 k] bf16 = 16 KB each, XOR-swizzled
                #pragma unroll
                for (int i = 0; i < 4; i++) {
                    int idx = tid + i * 256;          // 0..1023
                    int r = idx >> 3, gq = idx & 7;   // row, 16B-chunk
                    uint32_t so = swz128((uint32_t)(r * 128 + gq * 16));
                    const char* ahp = (const char*)(g_hhi + (size_t)r * CC + k0) + gq * 16;
                    const char* alp = (const char*)(g_hlo + (size_t)r * CC + k0) + gq * 16;
                    const char* bhp = (const char*)(g_wthi + (size_t)(col0B + r) * CC + k0) + gq * 16;
                    const char* blp = (const char*)(g_wtlo + (size_t)(col0B + r) * CC + k0) + gq * 16;
                    *(uint4*)(tiles + 0     + so) = *(const uint4*)ahp;
                    *(uint4*)(tiles + 16384 + so) = *(const uint4*)alp;
                    *(uint4*)(tiles + 32768 + so) = *(const uint4*)bhp;
                    *(uint4*)(tiles + 49152 + so) = *(const uint4*)blp;
                }
                __syncthreads();

                #pragma unroll
                for (int ks = 0; ks < 4; ks++) {
                    uint32_t ahi[2][4], alo[2][4];
                    #pragma unroll
                    for (int mf = 0; mf < 2; mf++) {
                        uint32_t off = swz128((uint32_t)((mrow + 16 * mf + aRow) * 128
                                                         + (2 * ks + aG) * 16));
                        LDSM_X4(ahi[mf], tAhi + off);
                        LDSM_X4(alo[mf], tAlo + off);
                    }
                    #pragma unroll
                    for (int nq = 0; nq < 4; nq++) {
                        uint32_t off = swz128((uint32_t)((ncol + 16 * nq + bRow) * 128
                                                         + (2 * ks + bG) * 16));
                        uint32_t bh[4], bl[4];
                        LDSM_X4(bh, tBhi + off);
                        LDSM_X4(bl, tBlo + off);
                        #pragma unroll
                        for (int mf = 0; mf < 2; mf++) {
                            MMA_BF16(acc[mf][2 * nq + 0], ahi[mf], bh[0], bh[1]);
                            MMA_BF16(acc[mf][2 * nq + 0], ahi[mf], bl[0], bl[1]);
                            MMA_BF16(acc[mf][2 * nq + 0], alo[mf], bh[0], bh[1]);
                            MMA_BF16(acc[mf][2 * nq + 1], ahi[mf], bh[2], bh[3]);
                            MMA_BF16(acc[mf][2 * nq + 1], ahi[mf], bl[2], bl[3]);
                            MMA_BF16(acc[mf][2 * nq + 1], alo[mf], bh[2], bh[3]);
                        }
                    }
                }
                __syncthreads();   // before restaging / phase A alias next step
            }

            // epilogue: write 128x128 fp32 tile to g_pp[zz]
            float* pq = g_pp + (size_t)zz * BB * PDIMP;
            #pragma unroll
            for (int mf = 0; mf < 2; mf++) {
                int r0 = mrow + 16 * mf + (lane >> 2);
                #pragma unroll
                for (int nb = 0; nb < 8; nb++) {
                    int c = col0B + ncol + nb * 8 + (lane & 3) * 2;
                    *(float2*)(pq + (size_t)r0 * PDIMP + c) =
                        make_float2(acc[mf][nb][0], acc[mf][nb][1]);
                    *(float2*)(pq + (size_t)(r0 + 8) * PDIMP + c) =
                        make_float2(acc[mf][nb][2], acc[mf][nb][3]);
                }
            }
        }
        grid_barrier();

        // ---------------- phase C: NTM step -----------------------------------
        if (cta < BB) {
            const int b = cta;

            // vectorized split-K reduce + bias over all PDIM cols (259 float4)
            for (int i4 = tid; i4 < 259; i4 += 256) {
                int i = i4 * 4;
                float4 s = *(const float4*)(g_ball + i);
                #pragma unroll
                for (int ks = 0; ks < SK; ks++) {
                    float4 v = *(const float4*)(g_pp + (size_t)ks * BB * PDIMP
                                                + (size_t)b * PDIMP + i);
                    s.x += v.x; s.y += v.y; s.z += v.z; s.w += v.w;
                }
                if (i < PR + PWD) {
                    *(float4*)(s_p + i) = s;
                } else {
                    *(float4*)(out + ((long long)b * TT + t) * OUTD + (i - PR - PWD)) = s;
                }
            }
            __syncthreads();
            if (tid < MM) {
                s_e[tid] = sigmoidf_(s_p[PR + PR + tid]);
                s_a[tid] = tanhf(s_p[PR + 2 * MM + 6 + tid]);
            }
            __syncthreads();

            address_fn(s_p, s_wr, s_mem, s_w, s_r8, tid);

            {
                int m = tid & (MM - 1);
                int half = tid >> 7;
                int n0 = half * 128;
                float a0 = 0.f, a1 = 0.f, a2 = 0.f, a3 = 0.f;
                #pragma unroll 4
                for (int n = n0; n < n0 + 128; n += 4) {
                    a0 += s_w[n + 0] * s_mem[(n + 0) * MM + m];
                    a1 += s_w[n + 1] * s_mem[(n + 1) * MM + m];
                    a2 += s_w[n + 2] * s_mem[(n + 2) * MM + m];
                    a3 += s_w[n + 3] * s_mem[(n + 3) * MM + m];
                }
                s_red[tid] = (a0 + a1) + (a2 + a3);
                __syncthreads();
                if (tid < MM) g_r[b * MM + tid] = s_red[tid] + s_red[tid + 128];
                __syncthreads();
            }

            address_fn(s_p + PR, s_ww, s_mem, s_w, s_r8, tid);

            {
                float4* sm4 = (float4*)s_mem;
                const float4* e4 = (const float4*)s_e;
                const float4* a4 = (const float4*)s_a;
                #pragma unroll 4
                for (int i = tid; i < NN * MM / 4; i += 256) {
                    int n = i >> 5;
                    int m4 = i & 31;
                    float wwn = s_w[n];
                    float4 old = sm4[i];
                    float4 ev = e4[m4];
                    float4 av = a4[m4];
                    float4 r;
                    r.x = old.x * (1.f - wwn * ev.x) + wwn * av.x;
                    r.y = old.y * (1.f - wwn * ev.y) + wwn * av.y;
                    r.z = old.z * (1.f - wwn * ev.z) + wwn * av.z;
                    r.w = old.w * (1.f - wwn * ev.w) + wwn * av.w;
                    sm4[i] = r;
                }
            }
        }
        grid_barrier();
    }
}

// -------- launch --------
extern "C" void kernel_launch(void* const* d_in, const int* in_sizes, int n_in,
                              void* d_out, int out_size) {
    const float* x        = (const float*)d_in[0];
    const float* Wc       = (const float*)d_in[1];
    const float* bc       = (const float*)d_in[2];
    const float* Wout     = (const float*)d_in[3];
    const float* bout     = (const float*)d_in[4];
    const float* Wr       = (const float*)d_in[5];
    const float* br       = (const float*)d_in[6];
    const float* Ww       = (const float*)d_in[7];
    const float* bw       = (const float*)d_in[8];
    const float* mem_init = (const float*)d_in[9];
    const float* read_init= (const float*)d_in[10];
    float* out = (float*)d_out;
    (void)in_sizes; (void)n_in; (void)out_size;

    const int DYNSMEM = 131072 + 65536;  // 196608 B
    cudaFuncSetAttribute(ntm_persistent_kernel,
                         cudaFuncAttributeMaxDynamicSharedMemorySize, DYNSMEM);

    pack_w_kernel<<<512, 256>>>(Wr, br, Ww, bw, Wout, bout);

    dim3 thr(16, 16);
    dim3 grid_x(CC / 128, (BB * TT) / 64);
    xproj_kernel<<<grid_x, thr>>>(x, Wc);

    ntm_persistent_kernel<<<NCTA, 256, DYNSMEM>>>(Wc, bc, mem_init, read_init, out);
}